// round 5
// baseline (speedup 1.0000x reference)
#include <cuda_runtime.h>

#define Dd 16
#define BATCH 32768
#define ROWS 16           // batch rows per block (2 per warp)
#define NTHREADS 256

typedef unsigned long long ull;

// stage-constant block layout (floats)
#define O_M0    0         // [j][c] 16x64
#define O_M0TD  1024      // dup [a][tx] pairs: a*32 + 2*tx, 2048
#define O_M1    3072      // [a][b] 64x64
#define O_M2    7168      // [j][c] 64x64
#define O_M2T   11264     // [c][b] 64x64
#define O_M3    15360     // [j][e] 64x16
#define O_M3D   16384     // dup [c][tx] pairs: c*32 + 2*tx, 2048
#define O_C0    18432
#define O_C1    18496
#define O_C2    18560
#define O_C3    18624
#define ST_FLOATS 18640

// per-warp (2-row) region: hXd 256, hYd 256, d0d 256, d2d 256, d1p 128
#define RP_FLOATS 1152
#define SMEM_FLOATS (ST_FLOATS + 8 * RP_FLOATS)
#define SMEM_BYTES (SMEM_FLOATS * 4)

__device__ float g_M[8 * ST_FLOATS];

__device__ __forceinline__ float sigm(float x) {
    return __fdividef(1.f, 1.f + __expf(-x));
}
__device__ __forceinline__ float tanh_f(float x) {
    x = fminf(fmaxf(x, -15.f), 15.f);
    float e = __expf(-2.f * x);
    return __fdividef(1.f - e, 1.f + e);
}
__device__ __forceinline__ ull pk2(float lo, float hi) {
    ull r; asm("mov.b64 %0,{%1,%2};" : "=l"(r) : "f"(lo), "f"(hi)); return r;
}
__device__ __forceinline__ void upk(ull v, float& lo, float& hi) {
    asm("mov.b64 {%0,%1},%2;" : "=f"(lo), "=f"(hi) : "l"(v));
}
__device__ __forceinline__ ull ffma2(ull a, ull b, ull c) {
    ull d; asm("fma.rn.f32x2 %0,%1,%2,%3;" : "=l"(d) : "l"(a), "l"(b), "l"(c)); return d;
}
__device__ __forceinline__ ull fmul2(ull a, ull b) {
    ull d; asm("mul.rn.f32x2 %0,%1,%2;" : "=l"(d) : "l"(a), "l"(b)); return d;
}
__device__ __forceinline__ ull fadd2(ull a, ull b) {
    ull d; asm("add.rn.f32x2 %0,%1,%2;" : "=l"(d) : "l"(a), "l"(b)); return d;
}

// ---------------- build kernel ----------------
__global__ void build_kernel(const float* __restrict__ ts,
    const float* __restrict__ W0, const float* __restrict__ b0, const float* __restrict__ g0, const float* __restrict__ gb0, const float* __restrict__ hb0,
    const float* __restrict__ W1, const float* __restrict__ b1, const float* __restrict__ g1, const float* __restrict__ gb1, const float* __restrict__ hb1,
    const float* __restrict__ W2, const float* __restrict__ b2, const float* __restrict__ g2, const float* __restrict__ gb2, const float* __restrict__ hb2,
    const float* __restrict__ W3, const float* __restrict__ b3, const float* __restrict__ g3, const float* __restrict__ gb3, const float* __restrict__ hb3)
{
    const int sidx = blockIdx.x;
    const int step = sidx >> 2, stg = sidx & 3;
    const float tA = ts[step];
    const float hstep = ts[step + 1] - tA;
    const float coef = (stg == 0) ? 0.f : ((stg == 3) ? hstep : 0.5f * hstep);
    const float t = tA + coef;
    float* base = g_M + sidx * ST_FLOATS;
    const int tid = threadIdx.x;

    for (int i = tid; i < 1024; i += NTHREADS) {
        int j = i >> 6, c = i & 63;
        float v = W0[i] * sigm(t * g0[c] + gb0[c]);
        base[O_M0 + i] = v;
        base[O_M0TD + c * 32 + 2 * j] = v;       // duplicated
        base[O_M0TD + c * 32 + 2 * j + 1] = v;
    }
    for (int i = tid; i < 4096; i += NTHREADS) {
        int c = i & 63;
        base[O_M1 + i] = W1[i] * sigm(t * g1[c] + gb1[c]);
    }
    for (int i = tid; i < 4096; i += NTHREADS) {
        int b = i >> 6, c = i & 63;
        float v = W2[i] * sigm(t * g2[c] + gb2[c]);
        base[O_M2 + i] = v;
        base[O_M2T + c * 64 + b] = v;
    }
    for (int i = tid; i < 1024; i += NTHREADS) {
        int j = i >> 4, e = i & 15;
        float v = W3[i] * sigm(t * g3[e] + gb3[e]);
        base[O_M3 + i] = v;
        base[O_M3D + j * 32 + 2 * e] = v;        // duplicated (c index == j)
        base[O_M3D + j * 32 + 2 * e + 1] = v;
    }
    if (tid < 64) {
        float s0 = sigm(t * g0[tid] + gb0[tid]);
        float s1 = sigm(t * g1[tid] + gb1[tid]);
        float s2 = sigm(t * g2[tid] + gb2[tid]);
        base[O_C0 + tid] = b0[tid] * s0 + t * hb0[tid];
        base[O_C1 + tid] = b1[tid] * s1 + t * hb1[tid];
        base[O_C2 + tid] = b2[tid] * s2 + t * hb2[tid];
        if (tid < 16) {
            float s3 = sigm(t * g3[tid] + gb3[tid]);
            base[O_C3 + tid] = b3[tid] * s3 + t * hb3[tid];
        }
    }
}

// forward layer: src (dup layout) -> dst (dup layout) + derivative buffer.
// DMODE 0: db in dup layout ([col][r] pairs). DMODE 1: db in pair layout ([k][r] float2).
template<int JN, int DMODE>
__device__ __forceinline__ void fwd64(const float* __restrict__ sm,
                                      const float* __restrict__ src, float* __restrict__ dst,
                                      float* __restrict__ db, int Moff, int Coff,
                                      int fjq, int fcg)
{
    ull acc[8];
    #pragma unroll
    for (int i = 0; i < 8; ++i) acc[i] = 0ull;
    #pragma unroll
    for (int i = 0; i < (JN >> 2); ++i) {
        const int j = 4 * i + fjq;
        const ulonglong2 m01 = *(const ulonglong2*)(sm + Moff + j * 64 + 4 * fcg);
        const ulonglong2 m23 = *(const ulonglong2*)(sm + Moff + j * 64 + 32 + 4 * fcg);
        const ull h0 = *(const ull*)(src + 4 * j);       // row0 value duplicated
        const ull h1 = *(const ull*)(src + 4 * j + 2);   // row1
        acc[0] = ffma2(h0, m01.x, acc[0]); acc[1] = ffma2(h0, m01.y, acc[1]);
        acc[2] = ffma2(h0, m23.x, acc[2]); acc[3] = ffma2(h0, m23.y, acc[3]);
        acc[4] = ffma2(h1, m01.x, acc[4]); acc[5] = ffma2(h1, m01.y, acc[5]);
        acc[6] = ffma2(h1, m23.x, acc[6]); acc[7] = ffma2(h1, m23.y, acc[7]);
    }
    #pragma unroll
    for (int m = 8; m <= 16; m <<= 1) {
        #pragma unroll
        for (int i = 0; i < 8; ++i)
            acc[i] = fadd2(acc[i], __shfl_xor_sync(0xffffffffu, acc[i], m));
    }
    const int cp = fjq;
    const int col0 = (cp < 2) ? (4 * fcg + 2 * cp) : (32 + 4 * fcg + 2 * (cp - 2));
    ull p0 = (cp == 0) ? acc[0] : ((cp == 1) ? acc[1] : ((cp == 2) ? acc[2] : acc[3]));
    ull p1 = (cp == 0) ? acc[4] : ((cp == 1) ? acc[5] : ((cp == 2) ? acc[6] : acc[7]));
    const float2 cb = *(const float2*)(sm + Coff + col0);
    float a0lo, a0hi, a1lo, a1hi;
    upk(p0, a0lo, a0hi); upk(p1, a1lo, a1hi);
    const float v00 = tanh_f(a0lo + cb.x), v01 = tanh_f(a0hi + cb.y);
    const float v10 = tanh_f(a1lo + cb.x), v11 = tanh_f(a1hi + cb.y);
    // dst duplicated: [col][r]
    *(ull*)(dst + 4 * col0)           = pk2(v00, v00);
    *(ull*)(dst + 4 * col0 + 2)       = pk2(v10, v10);
    *(ull*)(dst + 4 * (col0 + 1))     = pk2(v01, v01);
    *(ull*)(dst + 4 * (col0 + 1) + 2) = pk2(v11, v11);
    const float d00 = 1.f - v00 * v00, d01 = 1.f - v01 * v01;
    const float d10 = 1.f - v10 * v10, d11 = 1.f - v11 * v11;
    if (DMODE == 0) {
        *(ull*)(db + 4 * col0)           = pk2(d00, d00);
        *(ull*)(db + 4 * col0 + 2)       = pk2(d10, d10);
        *(ull*)(db + 4 * (col0 + 1))     = pk2(d01, d01);
        *(ull*)(db + 4 * (col0 + 1) + 2) = pk2(d11, d11);
    } else {
        const int k = col0 >> 1;
        *(ull*)(db + 4 * k)     = pk2(d00, d01);   // row0 pair
        *(ull*)(db + 4 * k + 2) = pk2(d10, d11);   // row1 pair
    }
}

// L3: 64 -> 16, no tanh; dx scalars written to dxb[e*2+r]
__device__ __forceinline__ void fwdL3(const float* __restrict__ sm,
                                      const float* __restrict__ src, float* __restrict__ dxb,
                                      int fjq, int fcg)
{
    ull a0 = 0ull, a1 = 0ull;
    #pragma unroll
    for (int i = 0; i < 16; ++i) {
        const int j = 4 * i + fjq;
        const ull m = *(const ull*)(sm + O_M3 + j * 16 + 2 * fcg);
        const ull h0 = *(const ull*)(src + 4 * j);
        const ull h1 = *(const ull*)(src + 4 * j + 2);
        a0 = ffma2(h0, m, a0);
        a1 = ffma2(h1, m, a1);
    }
    #pragma unroll
    for (int m = 8; m <= 16; m <<= 1) {
        a0 = fadd2(a0, __shfl_xor_sync(0xffffffffu, a0, m));
        a1 = fadd2(a1, __shfl_xor_sync(0xffffffffu, a1, m));
    }
    if (fjq == 0) {
        const float2 cb = *(const float2*)(sm + O_C3 + 2 * fcg);
        float x0l, x0h, x1l, x1h;
        upk(a0, x0l, x0h); upk(a1, x1l, x1h);
        *(ull*)(dxb + 4 * fcg)     = pk2(x0l + cb.x, x1l + cb.x);
        *(ull*)(dxb + 4 * fcg + 2) = pk2(x0h + cb.y, x1h + cb.y);
    }
}

// ---------------- main kernel ----------------
__global__ __launch_bounds__(NTHREADS, 2)
void traj_kernel(const float* __restrict__ ts, const float* __restrict__ x0,
                 float* __restrict__ out)
{
    extern __shared__ float sm[];
    const int tid  = threadIdx.x;
    const int lane = tid & 31;
    const int wrp  = tid >> 5;
    const int fjq  = lane >> 3, fcg = lane & 7;
    const int tr   = lane >> 4, tth = (lane >> 3) & 1, tcg = lane & 7;
    const int sr   = lane >> 4, se  = lane & 15;

    float* rb  = sm + ST_FLOATS + wrp * RP_FLOATS;
    float* hXd = rb;          // dup [j][r]
    float* hYd = rb + 256;
    float* d0d = rb + 512;    // dup
    float* d2d = rb + 768;    // dup
    float* d1p = rb + 1024;   // pair [k][r]

    const int grow0 = blockIdx.x * ROWS + wrp * 2;

    const float ts0 = ts[0], ts1 = ts[1], ts2 = ts[2];
    const float tst[3] = {ts0, ts1, ts2};

    float x_state = x0[(grow0 + sr) * Dd + se];
    float l_state = 0.f, v_state = 0.f;
    out[(grow0 + sr) * Dd + se] = x_state;

    #pragma unroll 1
    for (int step = 0; step < 2; ++step) {
        const float tA = tst[step];
        const float hstep = tst[step + 1] - tA;
        float ksx = 0.f, ksl = 0.f, ksv = 0.f, kxp = 0.f;

        #pragma unroll 1
        for (int stage = 0; stage < 4; ++stage) {
            if (stage != 2) {   // stage 2 shares t with stage 1
                __syncthreads();
                const int sidx = step * 4 + stage;
                const float4* __restrict__ src = (const float4*)(g_M + sidx * ST_FLOATS);
                float4* dst = (float4*)sm;
                #pragma unroll 1
                for (int i = tid; i < ST_FLOATS / 4; i += NTHREADS) dst[i] = __ldg(src + i);
                __syncthreads();
            }

            const float coef = (stage == 0) ? 0.f : ((stage == 3) ? hstep : 0.5f * hstep);
            const float wq = (stage == 1 || stage == 2) ? 2.f : 1.f;

            {   // stage input, duplicated
                const float xe = x_state + coef * kxp;
                *(ull*)(hXd + 4 * se + 2 * sr) = pk2(xe, xe);
            }
            __syncwarp();

            fwd64<16, 0>(sm, hXd, hYd, d0d, O_M0, O_C0, fjq, fcg);
            __syncwarp();
            fwd64<64, 1>(sm, hYd, hXd, d1p, O_M1, O_C1, fjq, fcg);
            __syncwarp();
            fwd64<64, 0>(sm, hXd, hYd, d2d, O_M2, O_C2, fjq, fcg);
            __syncwarp();
            fwdL3(sm, hYd, hXd, fjq, fcg);      // dx scalars -> hXd[0:32]
            __syncwarp();

            const float dx = hXd[2 * se + sr];

            // ===== tangent pass 1: A[tx][b] = sum_a M0T[a][tx] * (d0[a]*M1[a][b]) =====
            ull A[32];
            #pragma unroll
            for (int i = 0; i < 32; ++i) A[i] = 0ull;
            #pragma unroll 2
            for (int a = 0; a < 64; ++a) {
                const ull dd = *(const ull*)(d0d + 4 * a + 2 * tr);
                const ulonglong2 m01 = *(const ulonglong2*)(sm + O_M1 + a * 64 + 4 * tcg);
                const ulonglong2 m23 = *(const ulonglong2*)(sm + O_M1 + a * 64 + 32 + 4 * tcg);
                const ull mdA = fmul2(m01.x, dd), mdB = fmul2(m01.y, dd);
                const ull mdC = fmul2(m23.x, dd), mdD = fmul2(m23.y, dd);
                const float* mt = sm + O_M0TD + a * 32 + 16 * tth;
                const ulonglong2 u01 = *(const ulonglong2*)(mt);
                const ulonglong2 u23 = *(const ulonglong2*)(mt + 4);
                const ulonglong2 u45 = *(const ulonglong2*)(mt + 8);
                const ulonglong2 u67 = *(const ulonglong2*)(mt + 12);
                A[0]  = ffma2(u01.x, mdA, A[0]);  A[1]  = ffma2(u01.x, mdB, A[1]);
                A[2]  = ffma2(u01.x, mdC, A[2]);  A[3]  = ffma2(u01.x, mdD, A[3]);
                A[4]  = ffma2(u01.y, mdA, A[4]);  A[5]  = ffma2(u01.y, mdB, A[5]);
                A[6]  = ffma2(u01.y, mdC, A[6]);  A[7]  = ffma2(u01.y, mdD, A[7]);
                A[8]  = ffma2(u23.x, mdA, A[8]);  A[9]  = ffma2(u23.x, mdB, A[9]);
                A[10] = ffma2(u23.x, mdC, A[10]); A[11] = ffma2(u23.x, mdD, A[11]);
                A[12] = ffma2(u23.y, mdA, A[12]); A[13] = ffma2(u23.y, mdB, A[13]);
                A[14] = ffma2(u23.y, mdC, A[14]); A[15] = ffma2(u23.y, mdD, A[15]);
                A[16] = ffma2(u45.x, mdA, A[16]); A[17] = ffma2(u45.x, mdB, A[17]);
                A[18] = ffma2(u45.x, mdC, A[18]); A[19] = ffma2(u45.x, mdD, A[19]);
                A[20] = ffma2(u45.y, mdA, A[20]); A[21] = ffma2(u45.y, mdB, A[21]);
                A[22] = ffma2(u45.y, mdC, A[22]); A[23] = ffma2(u45.y, mdD, A[23]);
                A[24] = ffma2(u67.x, mdA, A[24]); A[25] = ffma2(u67.x, mdB, A[25]);
                A[26] = ffma2(u67.x, mdC, A[26]); A[27] = ffma2(u67.x, mdD, A[27]);
                A[28] = ffma2(u67.y, mdA, A[28]); A[29] = ffma2(u67.y, mdB, A[29]);
                A[30] = ffma2(u67.y, mdC, A[30]); A[31] = ffma2(u67.y, mdD, A[31]);
            }
            // scale by d1[b] (pair layout)
            {
                const ull s0 = *(const ull*)(d1p + 4 * (2 * tcg) + 2 * tr);
                const ull s1 = *(const ull*)(d1p + 4 * (2 * tcg + 1) + 2 * tr);
                const ull s2 = *(const ull*)(d1p + 4 * (16 + 2 * tcg) + 2 * tr);
                const ull s3 = *(const ull*)(d1p + 4 * (17 + 2 * tcg) + 2 * tr);
                #pragma unroll
                for (int k = 0; k < 8; ++k) {
                    A[k * 4 + 0] = fmul2(A[k * 4 + 0], s0);
                    A[k * 4 + 1] = fmul2(A[k * 4 + 1], s1);
                    A[k * 4 + 2] = fmul2(A[k * 4 + 2], s2);
                    A[k * 4 + 3] = fmul2(A[k * 4 + 3], s3);
                }
            }

            // ===== tangent pass 2: dl += sum_c (sum_tx M3[c][tx]*A[tx][:]) . (d2[c]*M2T[c][:]) =====
            ull dl2 = 0ull;
            #pragma unroll 2
            for (int c = 0; c < 64; ++c) {
                const ull dd = *(const ull*)(d2d + 4 * c + 2 * tr);
                const ulonglong2 w01 = *(const ulonglong2*)(sm + O_M2T + c * 64 + 4 * tcg);
                const ulonglong2 w23 = *(const ulonglong2*)(sm + O_M2T + c * 64 + 32 + 4 * tcg);
                const ull wdA = fmul2(w01.x, dd), wdB = fmul2(w01.y, dd);
                const ull wdC = fmul2(w23.x, dd), wdD = fmul2(w23.y, dd);
                const float* nt = sm + O_M3D + c * 32 + 16 * tth;
                const ulonglong2 n01 = *(const ulonglong2*)(nt);
                const ulonglong2 n23 = *(const ulonglong2*)(nt + 4);
                const ulonglong2 n45 = *(const ulonglong2*)(nt + 8);
                const ulonglong2 n67 = *(const ulonglong2*)(nt + 12);
                ull v0 = 0ull, v1 = 0ull, v2 = 0ull, v3 = 0ull;
                v0 = ffma2(n01.x, A[0],  v0); v1 = ffma2(n01.x, A[1],  v1);
                v2 = ffma2(n01.x, A[2],  v2); v3 = ffma2(n01.x, A[3],  v3);
                v0 = ffma2(n01.y, A[4],  v0); v1 = ffma2(n01.y, A[5],  v1);
                v2 = ffma2(n01.y, A[6],  v2); v3 = ffma2(n01.y, A[7],  v3);
                v0 = ffma2(n23.x, A[8],  v0); v1 = ffma2(n23.x, A[9],  v1);
                v2 = ffma2(n23.x, A[10], v2); v3 = ffma2(n23.x, A[11], v3);
                v0 = ffma2(n23.y, A[12], v0); v1 = ffma2(n23.y, A[13], v1);
                v2 = ffma2(n23.y, A[14], v2); v3 = ffma2(n23.y, A[15], v3);
                v0 = ffma2(n45.x, A[16], v0); v1 = ffma2(n45.x, A[17], v1);
                v2 = ffma2(n45.x, A[18], v2); v3 = ffma2(n45.x, A[19], v3);
                v0 = ffma2(n45.y, A[20], v0); v1 = ffma2(n45.y, A[21], v1);
                v2 = ffma2(n45.y, A[22], v2); v3 = ffma2(n45.y, A[23], v3);
                v0 = ffma2(n67.x, A[24], v0); v1 = ffma2(n67.x, A[25], v1);
                v2 = ffma2(n67.x, A[26], v2); v3 = ffma2(n67.x, A[27], v3);
                v0 = ffma2(n67.y, A[28], v0); v1 = ffma2(n67.y, A[29], v1);
                v2 = ffma2(n67.y, A[30], v2); v3 = ffma2(n67.y, A[31], v3);

                dl2 = ffma2(v0, wdA, dl2);
                dl2 = ffma2(v1, wdB, dl2);
                dl2 = ffma2(v2, wdC, dl2);
                dl2 = ffma2(v3, wdD, dl2);
            }

            float dlo, dhi; upk(dl2, dlo, dhi);
            float dl = dlo + dhi;
            float dv = dx * dx;
            #pragma unroll
            for (int m = 1; m <= 8; m <<= 1) {
                dl += __shfl_xor_sync(0xffffffffu, dl, m);
                dv += __shfl_xor_sync(0xffffffffu, dv, m);
            }
            dv *= 0.5f;

            ksx += wq * dx;
            ksl += wq * dl;
            ksv += wq * dv;
            kxp = dx;
        }

        const float scl = hstep * (1.f / 6.f);
        x_state += scl * ksx;
        l_state += scl * ksl;
        v_state += scl * ksv;
        out[(step + 1) * BATCH * Dd + (grow0 + sr) * Dd + se] = x_state;
    }

    if (se == 0) {
        const int base = 3 * BATCH * Dd;
        out[base + grow0 + sr] = l_state;
        out[base + BATCH + grow0 + sr] = fabsf(v_state);
        out[base + 2 * BATCH + grow0 + sr] = 0.f;
    }
}

extern "C" void kernel_launch(void* const* d_in, const int* in_sizes, int n_in,
                              void* d_out, int out_size) {
    const float* ts  = (const float*)d_in[0];
    const float* x0  = (const float*)d_in[1];
    const float* W0  = (const float*)d_in[2];
    const float* b0  = (const float*)d_in[3];
    const float* g0  = (const float*)d_in[4];
    const float* gb0 = (const float*)d_in[5];
    const float* hb0 = (const float*)d_in[6];
    const float* W1  = (const float*)d_in[7];
    const float* b1  = (const float*)d_in[8];
    const float* g1  = (const float*)d_in[9];
    const float* gb1 = (const float*)d_in[10];
    const float* hb1 = (const float*)d_in[11];
    const float* W2  = (const float*)d_in[12];
    const float* b2  = (const float*)d_in[13];
    const float* g2  = (const float*)d_in[14];
    const float* gb2 = (const float*)d_in[15];
    const float* hb2 = (const float*)d_in[16];
    const float* W3  = (const float*)d_in[17];
    const float* b3  = (const float*)d_in[18];
    const float* g3  = (const float*)d_in[19];
    const float* gb3 = (const float*)d_in[20];
    const float* hb3 = (const float*)d_in[21];
    float* out = (float*)d_out;

    build_kernel<<<8, NTHREADS>>>(ts,
        W0, b0, g0, gb0, hb0,
        W1, b1, g1, gb1, hb1,
        W2, b2, g2, gb2, hb2,
        W3, b3, g3, gb3, hb3);

    cudaFuncSetAttribute(traj_kernel, cudaFuncAttributeMaxDynamicSharedMemorySize, SMEM_BYTES);
    traj_kernel<<<BATCH / ROWS, NTHREADS, SMEM_BYTES>>>(ts, x0, out);
}

// round 6
// speedup vs baseline: 1.1170x; 1.1170x over previous
#include <cuda_runtime.h>
#include <cstdint>

#define Dd 16
#define BATCH 32768
#define ROWS 32           // batch rows per block (2 per warp, 16 warps)
#define NTHREADS 512

typedef unsigned long long ull;

// stage-constant block layout (floats) — identical to R4
#define O_M0   0          // [j][c] 16x64
#define O_M0T  1024       // [a][tx] 64x16
#define O_M1   2048       // [j][c] 64x64
#define O_M2   6144       // [j][c] 64x64
#define O_M2T  10240      // [c][b] 64x64
#define O_M3   14336      // [j][e] 64x16
#define O_C0   15360
#define O_C1   15424
#define O_C2   15488
#define O_C3   15552      // 16
#define ST_FLOATS 15568
#define ST_BYTES (ST_FLOATS * 4)

#define NCOPIES 5         // distinct t values across 8 RK stages

// smem layout: [mbar 16 floats][bufA][bufB][16 warps x RP_FLOATS]
#define MBAR_FLOATS 16
#define RP_FLOATS 640     // per warp (2 rows): hX,hY,d0,d1,d2 each 128 (interleaved [i*2+r])
#define SMEM_FLOATS (MBAR_FLOATS + 2 * ST_FLOATS + 16 * RP_FLOATS)
#define SMEM_BYTES (SMEM_FLOATS * 4)

__device__ float g_M[NCOPIES * ST_FLOATS];

__device__ __forceinline__ float sigm(float x) {
    return __fdividef(1.f, 1.f + __expf(-x));
}
__device__ __forceinline__ float tanh_f(float x) {
    x = fminf(fmaxf(x, -15.f), 15.f);
    float e = __expf(-2.f * x);
    return __fdividef(1.f - e, 1.f + e);
}
__device__ __forceinline__ ull pk2(float lo, float hi) {
    ull r; asm("mov.b64 %0,{%1,%2};" : "=l"(r) : "f"(lo), "f"(hi)); return r;
}
__device__ __forceinline__ ull pkdup(float v) { return pk2(v, v); }
__device__ __forceinline__ void upk(ull v, float& lo, float& hi) {
    asm("mov.b64 {%0,%1},%2;" : "=f"(lo), "=f"(hi) : "l"(v));
}
__device__ __forceinline__ ull ffma2(ull a, ull b, ull c) {
    ull d; asm("fma.rn.f32x2 %0,%1,%2,%3;" : "=l"(d) : "l"(a), "l"(b), "l"(c)); return d;
}
__device__ __forceinline__ ull fmul2(ull a, ull b) {
    ull d; asm("mul.rn.f32x2 %0,%1,%2;" : "=l"(d) : "l"(a), "l"(b)); return d;
}
__device__ __forceinline__ ull fadd2(ull a, ull b) {
    ull d; asm("add.rn.f32x2 %0,%1,%2;" : "=l"(d) : "l"(a), "l"(b)); return d;
}
__device__ __forceinline__ uint32_t smem_u32(const void* p) {
    uint32_t a;
    asm("{ .reg .u64 t; cvta.to.shared.u64 t, %1; cvt.u32.u64 %0, t; }" : "=r"(a) : "l"(p));
    return a;
}
__device__ __forceinline__ void issue_prefetch(uint32_t mbar, uint32_t dst, const float* src) {
    asm volatile("mbarrier.arrive.expect_tx.shared.b64 _, [%0], %1;"
                 :: "r"(mbar), "r"((uint32_t)ST_BYTES) : "memory");
    asm volatile("cp.async.bulk.shared::cta.global.mbarrier::complete_tx::bytes [%0], [%1], %2, [%3];"
                 :: "r"(dst), "l"(src), "r"((uint32_t)ST_BYTES), "r"(mbar) : "memory");
}
__device__ __forceinline__ void mbar_wait0(uint32_t mbar) {
    asm volatile(
        "{\n\t.reg .pred P;\n\t"
        "WL_%=:\n\t"
        "mbarrier.try_wait.parity.acquire.cta.shared::cta.b64 P, [%0], 0;\n\t"
        "@!P bra WL_%=;\n\t}"
        :: "r"(mbar) : "memory");
}

// ---------------- build kernel: one block per distinct t ----------------
__global__ void build_kernel(const float* __restrict__ ts,
    const float* __restrict__ W0, const float* __restrict__ b0, const float* __restrict__ g0, const float* __restrict__ gb0, const float* __restrict__ hb0,
    const float* __restrict__ W1, const float* __restrict__ b1, const float* __restrict__ g1, const float* __restrict__ gb1, const float* __restrict__ hb1,
    const float* __restrict__ W2, const float* __restrict__ b2, const float* __restrict__ g2, const float* __restrict__ gb2, const float* __restrict__ hb2,
    const float* __restrict__ W3, const float* __restrict__ b3, const float* __restrict__ g3, const float* __restrict__ gb3, const float* __restrict__ hb3)
{
    const int c = blockIdx.x;            // 0..4
    const float ts0 = ts[0], ts1 = ts[1], ts2 = ts[2];
    float t;
    if (c == 0) t = ts0;
    else if (c == 1) t = ts0 + 0.5f * (ts1 - ts0);
    else if (c == 2) t = ts1;
    else if (c == 3) t = ts1 + 0.5f * (ts2 - ts1);
    else t = ts2;

    float* base = g_M + c * ST_FLOATS;
    const int tid = threadIdx.x;

    for (int i = tid; i < 1024; i += blockDim.x) {
        int j = i >> 6, cc = i & 63;
        float v = W0[i] * sigm(t * g0[cc] + gb0[cc]);
        base[O_M0 + i] = v;
        base[O_M0T + cc * 16 + j] = v;
    }
    for (int i = tid; i < 4096; i += blockDim.x) {
        int cc = i & 63;
        base[O_M1 + i] = W1[i] * sigm(t * g1[cc] + gb1[cc]);
    }
    for (int i = tid; i < 4096; i += blockDim.x) {
        int b = i >> 6, cc = i & 63;
        float v = W2[i] * sigm(t * g2[cc] + gb2[cc]);
        base[O_M2 + i] = v;
        base[O_M2T + cc * 64 + b] = v;
    }
    for (int i = tid; i < 1024; i += blockDim.x) {
        int e = i & 15;
        base[O_M3 + i] = W3[i] * sigm(t * g3[e] + gb3[e]);
    }
    if (tid < 64) {
        float s0 = sigm(t * g0[tid] + gb0[tid]);
        float s1 = sigm(t * g1[tid] + gb1[tid]);
        float s2 = sigm(t * g2[tid] + gb2[tid]);
        base[O_C0 + tid] = b0[tid] * s0 + t * hb0[tid];
        base[O_C1 + tid] = b1[tid] * s1 + t * hb1[tid];
        base[O_C2 + tid] = b2[tid] * s2 + t * hb2[tid];
        if (tid < 16) {
            float s3 = sigm(t * g3[tid] + gb3[tid]);
            base[O_C3 + tid] = b3[tid] * s3 + t * hb3[tid];
        }
    }
}

// forward layer (JN inputs -> 64 outputs + tanh + deriv); 2 rows per warp. (verbatim R4)
__device__ __forceinline__ void fwd64(const float* __restrict__ mb,
                                      const float* __restrict__ src, float* __restrict__ dst,
                                      float* __restrict__ db, int Moff, int Coff, int JN,
                                      int fjq, int fcg)
{
    ull acc[8];
    #pragma unroll
    for (int i = 0; i < 8; ++i) acc[i] = 0ull;
    const int niter = JN >> 2;
    #pragma unroll 4
    for (int i = 0; i < niter; ++i) {
        const int j = 4 * i + fjq;
        const float4 m01 = *(const float4*)(mb + Moff + j * 64 + 4 * fcg);
        const float4 m23 = *(const float4*)(mb + Moff + j * 64 + 32 + 4 * fcg);
        const float2 hh = *(const float2*)(src + 2 * j);
        const ull h0 = pkdup(hh.x), h1 = pkdup(hh.y);
        const ull cA = pk2(m01.x, m01.y), cB = pk2(m01.z, m01.w);
        const ull cC = pk2(m23.x, m23.y), cD = pk2(m23.z, m23.w);
        acc[0] = ffma2(h0, cA, acc[0]); acc[1] = ffma2(h0, cB, acc[1]);
        acc[2] = ffma2(h0, cC, acc[2]); acc[3] = ffma2(h0, cD, acc[3]);
        acc[4] = ffma2(h1, cA, acc[4]); acc[5] = ffma2(h1, cB, acc[5]);
        acc[6] = ffma2(h1, cC, acc[6]); acc[7] = ffma2(h1, cD, acc[7]);
    }
    #pragma unroll
    for (int m = 8; m <= 16; m <<= 1) {
        #pragma unroll
        for (int i = 0; i < 8; ++i)
            acc[i] = fadd2(acc[i], __shfl_xor_sync(0xffffffffu, acc[i], m));
    }
    const int cp = fjq;
    const int col0 = (cp < 2) ? (4 * fcg + 2 * cp) : (32 + 4 * fcg + 2 * (cp - 2));
    ull p0 = (cp == 0) ? acc[0] : ((cp == 1) ? acc[1] : ((cp == 2) ? acc[2] : acc[3]));
    ull p1 = (cp == 0) ? acc[4] : ((cp == 1) ? acc[5] : ((cp == 2) ? acc[6] : acc[7]));
    const float2 cb = *(const float2*)(mb + Coff + col0);
    float a0lo, a0hi, a1lo, a1hi;
    upk(p0, a0lo, a0hi); upk(p1, a1lo, a1hi);
    float v00 = tanh_f(a0lo + cb.x), v01 = tanh_f(a0hi + cb.y);
    float v10 = tanh_f(a1lo + cb.x), v11 = tanh_f(a1hi + cb.y);
    *(float2*)(dst + 2 * col0)     = make_float2(v00, v10);
    *(float2*)(dst + 2 * col0 + 2) = make_float2(v01, v11);
    *(float2*)(db  + 2 * col0)     = make_float2(1.f - v00 * v00, 1.f - v10 * v10);
    *(float2*)(db  + 2 * col0 + 2) = make_float2(1.f - v01 * v01, 1.f - v11 * v11);
}

// L3: 64 -> 16, no tanh; dx written to dxbuf[e*2+r] (verbatim R4)
__device__ __forceinline__ void fwdL3(const float* __restrict__ mb,
                                      const float* __restrict__ src, float* __restrict__ dxbuf,
                                      int fjq, int fcg)
{
    ull a0 = 0ull, a1 = 0ull;
    #pragma unroll 4
    for (int i = 0; i < 16; ++i) {
        const int j = 4 * i + fjq;
        const float2 m = *(const float2*)(mb + O_M3 + j * 16 + 2 * fcg);
        const float2 hh = *(const float2*)(src + 2 * j);
        const ull mm = pk2(m.x, m.y);
        a0 = ffma2(pkdup(hh.x), mm, a0);
        a1 = ffma2(pkdup(hh.y), mm, a1);
    }
    #pragma unroll
    for (int m = 8; m <= 16; m <<= 1) {
        a0 = fadd2(a0, __shfl_xor_sync(0xffffffffu, a0, m));
        a1 = fadd2(a1, __shfl_xor_sync(0xffffffffu, a1, m));
    }
    if (fjq == 0) {
        const float2 cb = *(const float2*)(mb + O_C3 + 2 * fcg);
        float x0l, x0h, x1l, x1h;
        upk(a0, x0l, x0h); upk(a1, x1l, x1h);
        *(float4*)(dxbuf + 4 * fcg) =
            make_float4(x0l + cb.x, x1l + cb.x, x0h + cb.y, x1h + cb.y);
    }
}

// ---------------- main kernel ----------------
__global__ __launch_bounds__(NTHREADS, 1)
void traj_kernel(const float* __restrict__ ts, const float* __restrict__ x0,
                 float* __restrict__ out)
{
    extern __shared__ float sm[];
    float* bufA = sm + MBAR_FLOATS;
    float* bufB = bufA + ST_FLOATS;
    float* rows = bufB + ST_FLOATS;

    const int tid  = threadIdx.x;
    const int lane = tid & 31;
    const int wrp  = tid >> 5;
    const int fjq  = lane >> 3, fcg = lane & 7;
    const int tr   = lane >> 4, tth = (lane >> 3) & 1, tcg = lane & 7;
    const int sr   = lane >> 4, se  = lane & 15;

    float* rb  = rows + wrp * RP_FLOATS;
    float* hX  = rb;         // [i*2+r]
    float* hY  = rb + 128;
    float* d0b = rb + 256;
    float* d1b = rb + 384;
    float* d2b = rb + 512;

    const uint32_t smb = smem_u32(sm);
    const uint32_t bufAu = smem_u32(bufA), bufBu = smem_u32(bufB);

    // init mbarriers + kick off first two prefetches
    if (tid == 0) {
        #pragma unroll
        for (int c = 0; c < NCOPIES; ++c)
            asm volatile("mbarrier.init.shared.b64 [%0], 1;" :: "r"(smb + c * 8) : "memory");
    }
    __syncthreads();
    if (tid == 0) {
        issue_prefetch(smb + 0 * 8, bufAu, g_M + 0 * ST_FLOATS);
        issue_prefetch(smb + 1 * 8, bufBu, g_M + 1 * ST_FLOATS);
    }

    const int grow0 = blockIdx.x * ROWS + wrp * 2;

    const float ts0 = ts[0], ts1 = ts[1], ts2 = ts[2];
    const float tst[3] = {ts0, ts1, ts2};

    float x_state = x0[(grow0 + sr) * Dd + se];
    float l_state = 0.f, v_state = 0.f;
    out[(grow0 + sr) * Dd + se] = x_state;

    int prev_c = -1;
    const float* mb = bufA;

    #pragma unroll 1
    for (int step = 0; step < 2; ++step) {
        const float tA = tst[step];
        const float hstep = tst[step + 1] - tA;
        float ksx = 0.f, ksl = 0.f, ksv = 0.f, kxp = 0.f;

        #pragma unroll 1
        for (int stage = 0; stage < 4; ++stage) {
            const int cidx = step * 2 + ((stage == 0) ? 0 : ((stage == 3) ? 2 : 1));
            if (cidx != prev_c) {
                __syncthreads();   // everyone done with buffer (cidx+1)&1's old contents
                if (tid == 0 && cidx >= 1 && cidx + 1 < NCOPIES) {
                    const uint32_t dst = ((cidx + 1) & 1) ? bufBu : bufAu;
                    issue_prefetch(smb + (cidx + 1) * 8, dst, g_M + (cidx + 1) * ST_FLOATS);
                }
                mbar_wait0(smb + cidx * 8);
                mb = (cidx & 1) ? bufB : bufA;
                prev_c = cidx;
            }

            const float coef = (stage == 0) ? 0.f : ((stage == 3) ? hstep : 0.5f * hstep);
            const float wq = (stage == 1 || stage == 2) ? 2.f : 1.f;

            hX[2 * se + sr] = x_state + coef * kxp;
            __syncwarp();

            fwd64(mb, hX, hY, d0b, O_M0, O_C0, 16, fjq, fcg);
            __syncwarp();
            fwd64(mb, hY, hX, d1b, O_M1, O_C1, 64, fjq, fcg);
            __syncwarp();
            fwd64(mb, hX, hY, d2b, O_M2, O_C2, 64, fjq, fcg);
            __syncwarp();
            fwdL3(mb, hY, hX, fjq, fcg);        // dx -> hX[e*2+r]
            __syncwarp();

            const float dx = hX[2 * se + sr];

            // ===== tangent pass 1: A[tx][b] = sum_a (M0T[a][tx]*d0[a]) * M1[a][b] =====
            ull A[32];
            #pragma unroll
            for (int i = 0; i < 32; ++i) A[i] = 0ull;
            #pragma unroll 2
            for (int a = 0; a < 64; ++a) {
                const float4 mt0 = *(const float4*)(mb + O_M0T + a * 16 + 8 * tth);
                const float4 mt1 = *(const float4*)(mb + O_M0T + a * 16 + 8 * tth + 4);
                const float dd = d0b[2 * a + tr];
                const float4 m01 = *(const float4*)(mb + O_M1 + a * 64 + 4 * tcg);
                const float4 m23 = *(const float4*)(mb + O_M1 + a * 64 + 32 + 4 * tcg);
                const ull cA = pk2(m01.x, m01.y), cB = pk2(m01.z, m01.w);
                const ull cC = pk2(m23.x, m23.y), cD = pk2(m23.z, m23.w);
                ull ud;
                ud = pkdup(mt0.x * dd);
                A[0]  = ffma2(ud, cA, A[0]);  A[1]  = ffma2(ud, cB, A[1]);
                A[2]  = ffma2(ud, cC, A[2]);  A[3]  = ffma2(ud, cD, A[3]);
                ud = pkdup(mt0.y * dd);
                A[4]  = ffma2(ud, cA, A[4]);  A[5]  = ffma2(ud, cB, A[5]);
                A[6]  = ffma2(ud, cC, A[6]);  A[7]  = ffma2(ud, cD, A[7]);
                ud = pkdup(mt0.z * dd);
                A[8]  = ffma2(ud, cA, A[8]);  A[9]  = ffma2(ud, cB, A[9]);
                A[10] = ffma2(ud, cC, A[10]); A[11] = ffma2(ud, cD, A[11]);
                ud = pkdup(mt0.w * dd);
                A[12] = ffma2(ud, cA, A[12]); A[13] = ffma2(ud, cB, A[13]);
                A[14] = ffma2(ud, cC, A[14]); A[15] = ffma2(ud, cD, A[15]);
                ud = pkdup(mt1.x * dd);
                A[16] = ffma2(ud, cA, A[16]); A[17] = ffma2(ud, cB, A[17]);
                A[18] = ffma2(ud, cC, A[18]); A[19] = ffma2(ud, cD, A[19]);
                ud = pkdup(mt1.y * dd);
                A[20] = ffma2(ud, cA, A[20]); A[21] = ffma2(ud, cB, A[21]);
                A[22] = ffma2(ud, cC, A[22]); A[23] = ffma2(ud, cD, A[23]);
                ud = pkdup(mt1.z * dd);
                A[24] = ffma2(ud, cA, A[24]); A[25] = ffma2(ud, cB, A[25]);
                A[26] = ffma2(ud, cC, A[26]); A[27] = ffma2(ud, cD, A[27]);
                ud = pkdup(mt1.w * dd);
                A[28] = ffma2(ud, cA, A[28]); A[29] = ffma2(ud, cB, A[29]);
                A[30] = ffma2(ud, cC, A[30]); A[31] = ffma2(ud, cD, A[31]);
            }
            // scale by d1[b]
            {
                const int b0 = 4 * tcg, b2 = 32 + 4 * tcg;
                const ull s0 = pk2(d1b[2 * b0 + tr],       d1b[2 * (b0 + 1) + tr]);
                const ull s1 = pk2(d1b[2 * (b0 + 2) + tr], d1b[2 * (b0 + 3) + tr]);
                const ull s2 = pk2(d1b[2 * b2 + tr],       d1b[2 * (b2 + 1) + tr]);
                const ull s3 = pk2(d1b[2 * (b2 + 2) + tr], d1b[2 * (b2 + 3) + tr]);
                #pragma unroll
                for (int k = 0; k < 8; ++k) {
                    A[k * 4 + 0] = fmul2(A[k * 4 + 0], s0);
                    A[k * 4 + 1] = fmul2(A[k * 4 + 1], s1);
                    A[k * 4 + 2] = fmul2(A[k * 4 + 2], s2);
                    A[k * 4 + 3] = fmul2(A[k * 4 + 3], s3);
                }
            }

            // ===== tangent pass 2: dl += sum_c (sum_tx n[c][tx]*A[tx][:]) . M2T[c][:] =====
            ull dl2 = 0ull;
            #pragma unroll 2
            for (int c = 0; c < 64; ++c) {
                const float4 n0 = *(const float4*)(mb + O_M3 + c * 16 + 8 * tth);
                const float4 n1 = *(const float4*)(mb + O_M3 + c * 16 + 8 * tth + 4);
                const float d2v = d2b[2 * c + tr];
                const float4 w01 = *(const float4*)(mb + O_M2T + c * 64 + 4 * tcg);
                const float4 w23 = *(const float4*)(mb + O_M2T + c * 64 + 32 + 4 * tcg);
                ull v0 = 0ull, v1 = 0ull, v2 = 0ull, v3 = 0ull;
                ull nd;
                nd = pkdup(n0.x * d2v);
                v0 = ffma2(nd, A[0],  v0); v1 = ffma2(nd, A[1],  v1);
                v2 = ffma2(nd, A[2],  v2); v3 = ffma2(nd, A[3],  v3);
                nd = pkdup(n0.y * d2v);
                v0 = ffma2(nd, A[4],  v0); v1 = ffma2(nd, A[5],  v1);
                v2 = ffma2(nd, A[6],  v2); v3 = ffma2(nd, A[7],  v3);
                nd = pkdup(n0.z * d2v);
                v0 = ffma2(nd, A[8],  v0); v1 = ffma2(nd, A[9],  v1);
                v2 = ffma2(nd, A[10], v2); v3 = ffma2(nd, A[11], v3);
                nd = pkdup(n0.w * d2v);
                v0 = ffma2(nd, A[12], v0); v1 = ffma2(nd, A[13], v1);
                v2 = ffma2(nd, A[14], v2); v3 = ffma2(nd, A[15], v3);
                nd = pkdup(n1.x * d2v);
                v0 = ffma2(nd, A[16], v0); v1 = ffma2(nd, A[17], v1);
                v2 = ffma2(nd, A[18], v2); v3 = ffma2(nd, A[19], v3);
                nd = pkdup(n1.y * d2v);
                v0 = ffma2(nd, A[20], v0); v1 = ffma2(nd, A[21], v1);
                v2 = ffma2(nd, A[22], v2); v3 = ffma2(nd, A[23], v3);
                nd = pkdup(n1.z * d2v);
                v0 = ffma2(nd, A[24], v0); v1 = ffma2(nd, A[25], v1);
                v2 = ffma2(nd, A[26], v2); v3 = ffma2(nd, A[27], v3);
                nd = pkdup(n1.w * d2v);
                v0 = ffma2(nd, A[28], v0); v1 = ffma2(nd, A[29], v1);
                v2 = ffma2(nd, A[30], v2); v3 = ffma2(nd, A[31], v3);

                dl2 = ffma2(v0, pk2(w01.x, w01.y), dl2);
                dl2 = ffma2(v1, pk2(w01.z, w01.w), dl2);
                dl2 = ffma2(v2, pk2(w23.x, w23.y), dl2);
                dl2 = ffma2(v3, pk2(w23.z, w23.w), dl2);
            }

            float dlo, dhi; upk(dl2, dlo, dhi);
            float dl = dlo + dhi;
            float dv = dx * dx;
            #pragma unroll
            for (int m = 1; m <= 8; m <<= 1) {
                dl += __shfl_xor_sync(0xffffffffu, dl, m);
                dv += __shfl_xor_sync(0xffffffffu, dv, m);
            }
            dv *= 0.5f;

            ksx += wq * dx;
            ksl += wq * dl;
            ksv += wq * dv;
            kxp = dx;
        }

        const float scl = hstep * (1.f / 6.f);
        x_state += scl * ksx;
        l_state += scl * ksl;
        v_state += scl * ksv;
        out[(step + 1) * BATCH * Dd + (grow0 + sr) * Dd + se] = x_state;
    }

    if (se == 0) {
        const int base = 3 * BATCH * Dd;
        out[base + grow0 + sr] = l_state;
        out[base + BATCH + grow0 + sr] = fabsf(v_state);
        out[base + 2 * BATCH + grow0 + sr] = 0.f;
    }
}

extern "C" void kernel_launch(void* const* d_in, const int* in_sizes, int n_in,
                              void* d_out, int out_size) {
    const float* ts  = (const float*)d_in[0];
    const float* x0  = (const float*)d_in[1];
    const float* W0  = (const float*)d_in[2];
    const float* b0  = (const float*)d_in[3];
    const float* g0  = (const float*)d_in[4];
    const float* gb0 = (const float*)d_in[5];
    const float* hb0 = (const float*)d_in[6];
    const float* W1  = (const float*)d_in[7];
    const float* b1  = (const float*)d_in[8];
    const float* g1  = (const float*)d_in[9];
    const float* gb1 = (const float*)d_in[10];
    const float* hb1 = (const float*)d_in[11];
    const float* W2  = (const float*)d_in[12];
    const float* b2  = (const float*)d_in[13];
    const float* g2  = (const float*)d_in[14];
    const float* gb2 = (const float*)d_in[15];
    const float* hb2 = (const float*)d_in[16];
    const float* W3  = (const float*)d_in[17];
    const float* b3  = (const float*)d_in[18];
    const float* g3  = (const float*)d_in[19];
    const float* gb3 = (const float*)d_in[20];
    const float* hb3 = (const float*)d_in[21];
    float* out = (float*)d_out;

    build_kernel<<<NCOPIES, 256>>>(ts,
        W0, b0, g0, gb0, hb0,
        W1, b1, g1, gb1, hb1,
        W2, b2, g2, gb2, hb2,
        W3, b3, g3, gb3, hb3);

    cudaFuncSetAttribute(traj_kernel, cudaFuncAttributeMaxDynamicSharedMemorySize, SMEM_BYTES);
    traj_kernel<<<BATCH / ROWS, NTHREADS, SMEM_BYTES>>>(ts, x0, out);
}

// round 8
// speedup vs baseline: 2.3601x; 2.1129x over previous
#include <cuda_runtime.h>
#include <cuda_bf16.h>
#include <cstdint>

#define Dd 16
#define BATCH 32768

typedef unsigned long long ull;

// ================= forward-stage constant block (fp32) =================
#define FO_M0 0
#define FO_M1 1024
#define FO_M2 5120
#define FO_M3 9216
#define FO_C0 10240
#define FO_C1 10304
#define FO_C2 10368
#define FO_C3 10432
#define FST_FLOATS 10448

#define NT 5   // distinct t values

#define TF_STRIDE 68
#define TF_M3T    (16 * TF_STRIDE)          // 1088
#define TF_FLOATS (2 * 16 * TF_STRIDE)      // 2176

#define BP_STRIDE 72                        // bf16 per row
#define BP_ELEMS  (64 * BP_STRIDE)          // 4608 bf16 per plane

__device__ float g_F[NT * FST_FLOATS];
__device__ float g_Tf[NT * TF_FLOATS];                 // M0f[tx][a], M3T[tx][c], stride 68
__device__ __nv_bfloat16 g_Tbf[NT * 4 * BP_ELEMS];     // planes: B1h,B1l,B2h,B2l ([64][72])
__device__ float g_d[8ull * BATCH * 192];              // [e][row][d0|d1|d2]
__device__ float g_dl[8 * BATCH];

__device__ __forceinline__ float sigm(float x) {
    return __fdividef(1.f, 1.f + __expf(-x));
}
__device__ __forceinline__ float tanh_f(float x) {
    x = fminf(fmaxf(x, -15.f), 15.f);
    float e = __expf(-2.f * x);
    return __fdividef(1.f - e, 1.f + e);
}
__device__ __forceinline__ ull pk2(float lo, float hi) {
    ull r; asm("mov.b64 %0,{%1,%2};" : "=l"(r) : "f"(lo), "f"(hi)); return r;
}
__device__ __forceinline__ ull pkdup(float v) { return pk2(v, v); }
__device__ __forceinline__ void upk(ull v, float& lo, float& hi) {
    asm("mov.b64 {%0,%1},%2;" : "=f"(lo), "=f"(hi) : "l"(v));
}
__device__ __forceinline__ ull ffma2(ull a, ull b, ull c) {
    ull d; asm("fma.rn.f32x2 %0,%1,%2,%3;" : "=l"(d) : "l"(a), "l"(b), "l"(c)); return d;
}
__device__ __forceinline__ ull fadd2(ull a, ull b) {
    ull d; asm("add.rn.f32x2 %0,%1,%2;" : "=l"(d) : "l"(a), "l"(b)); return d;
}
__device__ __forceinline__ uint32_t smem_u32(const void* p) {
    uint32_t a;
    asm("{ .reg .u64 t; cvta.to.shared.u64 t, %1; cvt.u32.u64 %0, t; }" : "=r"(a) : "l"(p));
    return a;
}
// pack (lo=v0, hi=v1) into bf16x2, return hi-plane reg, output lo-plane residual reg
__device__ __forceinline__ uint32_t bf2_split(float v0, float v1, uint32_t& lo) {
    uint32_t h;
    asm("cvt.rn.bf16x2.f32 %0, %1, %2;" : "=r"(h) : "f"(v1), "f"(v0));
    float r0 = v0 - __uint_as_float(h << 16);
    float r1 = v1 - __uint_as_float(h & 0xFFFF0000u);
    asm("cvt.rn.bf16x2.f32 %0, %1, %2;" : "=r"(lo) : "f"(r1), "f"(r0));
    return h;
}
__device__ __forceinline__ void ldmx2(uint32_t addr, uint32_t& r0, uint32_t& r1) {
    asm volatile("ldmatrix.sync.aligned.m8n8.x2.trans.shared.b16 {%0,%1}, [%2];"
                 : "=r"(r0), "=r"(r1) : "r"(addr));
}
__device__ __forceinline__ void mma16816(float* c, const uint32_t* a, uint32_t b0, uint32_t b1) {
    asm("mma.sync.aligned.m16n8k16.row.col.f32.bf16.bf16.f32 "
        "{%0,%1,%2,%3}, {%4,%5,%6,%7}, {%8,%9}, {%0,%1,%2,%3};"
        : "+f"(c[0]), "+f"(c[1]), "+f"(c[2]), "+f"(c[3])
        : "r"(a[0]), "r"(a[1]), "r"(a[2]), "r"(a[3]), "r"(b0), "r"(b1));
}

// ---------------- build kernel: one block per distinct t ----------------
__global__ void build_kernel(const float* __restrict__ ts,
    const float* __restrict__ W0, const float* __restrict__ b0, const float* __restrict__ g0, const float* __restrict__ gb0, const float* __restrict__ hb0,
    const float* __restrict__ W1, const float* __restrict__ b1, const float* __restrict__ g1, const float* __restrict__ gb1, const float* __restrict__ hb1,
    const float* __restrict__ W2, const float* __restrict__ b2, const float* __restrict__ g2, const float* __restrict__ gb2, const float* __restrict__ hb2,
    const float* __restrict__ W3, const float* __restrict__ b3, const float* __restrict__ g3, const float* __restrict__ gb3, const float* __restrict__ hb3)
{
    const int tt = blockIdx.x;
    const float ts0 = ts[0], ts1 = ts[1], ts2 = ts[2];
    float t;
    if (tt == 0) t = ts0;
    else if (tt == 1) t = ts0 + 0.5f * (ts1 - ts0);
    else if (tt == 2) t = ts1;
    else if (tt == 3) t = ts1 + 0.5f * (ts2 - ts1);
    else t = ts2;

    float* fb = g_F + tt * FST_FLOATS;
    float* tf = g_Tf + tt * TF_FLOATS;
    __nv_bfloat16* bp = g_Tbf + tt * 4 * BP_ELEMS;
    const int tid = threadIdx.x;

    for (int i = tid; i < 1024; i += blockDim.x) {
        int j = i >> 6, c = i & 63;
        float v = W0[i] * sigm(t * g0[c] + gb0[c]);
        fb[FO_M0 + i] = v;
        tf[j * TF_STRIDE + c] = v;                 // M0f[tx=j][a=c]
    }
    for (int i = tid; i < 4096; i += blockDim.x) {
        int a = i >> 6, b = i & 63;
        float v = W1[i] * sigm(t * g1[b] + gb1[b]);
        fb[FO_M1 + i] = v;
        __nv_bfloat16 h = __float2bfloat16_rn(v);
        __nv_bfloat16 l = __float2bfloat16_rn(v - __bfloat162float(h));
        bp[0 * BP_ELEMS + a * BP_STRIDE + b] = h;  // B1[k=a][n=b]
        bp[1 * BP_ELEMS + a * BP_STRIDE + b] = l;
    }
    for (int i = tid; i < 4096; i += blockDim.x) {
        int b = i >> 6, c = i & 63;
        float v = W2[i] * sigm(t * g2[c] + gb2[c]);
        fb[FO_M2 + i] = v;
        __nv_bfloat16 h = __float2bfloat16_rn(v);
        __nv_bfloat16 l = __float2bfloat16_rn(v - __bfloat162float(h));
        bp[2 * BP_ELEMS + c * BP_STRIDE + b] = h;  // B2[k=c][n=b] = M2[b][c]
        bp[3 * BP_ELEMS + c * BP_STRIDE + b] = l;
    }
    for (int i = tid; i < 1024; i += blockDim.x) {
        int c = i >> 4, e = i & 15;
        float v = W3[i] * sigm(t * g3[e] + gb3[e]);
        fb[FO_M3 + i] = v;
        tf[TF_M3T + e * TF_STRIDE + c] = v;        // M3T[tx=e][c]
    }
    if (tid < 64) {
        float s0 = sigm(t * g0[tid] + gb0[tid]);
        float s1 = sigm(t * g1[tid] + gb1[tid]);
        float s2 = sigm(t * g2[tid] + gb2[tid]);
        fb[FO_C0 + tid] = b0[tid] * s0 + t * hb0[tid];
        fb[FO_C1 + tid] = b1[tid] * s1 + t * hb1[tid];
        fb[FO_C2 + tid] = b2[tid] * s2 + t * hb2[tid];
        if (tid < 16) {
            float s3 = sigm(t * g3[tid] + gb3[tid]);
            fb[FO_C3 + tid] = b3[tid] * s3 + t * hb3[tid];
        }
    }
}

// ================= forward kernel =================
#define FROWS 16
#define FNT 256
#define FRP 256
#define FSMEM_BYTES ((FST_FLOATS + 8 * FRP) * 4)

__device__ __forceinline__ void fwd64g(const float* __restrict__ mb,
                                       const float* __restrict__ src, float* __restrict__ dst,
                                       float* __restrict__ gd, int Moff, int Coff, int JN,
                                       int fjq, int fcg)
{
    ull acc[8];
    #pragma unroll
    for (int i = 0; i < 8; ++i) acc[i] = 0ull;
    const int niter = JN >> 2;
    #pragma unroll 4
    for (int i = 0; i < niter; ++i) {
        const int j = 4 * i + fjq;
        const float4 m01 = *(const float4*)(mb + Moff + j * 64 + 4 * fcg);
        const float4 m23 = *(const float4*)(mb + Moff + j * 64 + 32 + 4 * fcg);
        const float2 hh = *(const float2*)(src + 2 * j);
        const ull h0 = pkdup(hh.x), h1 = pkdup(hh.y);
        const ull cA = pk2(m01.x, m01.y), cB = pk2(m01.z, m01.w);
        const ull cC = pk2(m23.x, m23.y), cD = pk2(m23.z, m23.w);
        acc[0] = ffma2(h0, cA, acc[0]); acc[1] = ffma2(h0, cB, acc[1]);
        acc[2] = ffma2(h0, cC, acc[2]); acc[3] = ffma2(h0, cD, acc[3]);
        acc[4] = ffma2(h1, cA, acc[4]); acc[5] = ffma2(h1, cB, acc[5]);
        acc[6] = ffma2(h1, cC, acc[6]); acc[7] = ffma2(h1, cD, acc[7]);
    }
    #pragma unroll
    for (int m = 8; m <= 16; m <<= 1) {
        #pragma unroll
        for (int i = 0; i < 8; ++i)
            acc[i] = fadd2(acc[i], __shfl_xor_sync(0xffffffffu, acc[i], m));
    }
    const int cp = fjq;
    const int col0 = (cp < 2) ? (4 * fcg + 2 * cp) : (32 + 4 * fcg + 2 * (cp - 2));
    ull p0 = (cp == 0) ? acc[0] : ((cp == 1) ? acc[1] : ((cp == 2) ? acc[2] : acc[3]));
    ull p1 = (cp == 0) ? acc[4] : ((cp == 1) ? acc[5] : ((cp == 2) ? acc[6] : acc[7]));
    const float2 cb = *(const float2*)(mb + Coff + col0);
    float a0lo, a0hi, a1lo, a1hi;
    upk(p0, a0lo, a0hi); upk(p1, a1lo, a1hi);
    float v00 = tanh_f(a0lo + cb.x), v01 = tanh_f(a0hi + cb.y);
    float v10 = tanh_f(a1lo + cb.x), v11 = tanh_f(a1hi + cb.y);
    *(float2*)(dst + 2 * col0)     = make_float2(v00, v10);
    *(float2*)(dst + 2 * col0 + 2) = make_float2(v01, v11);
    *(float2*)(gd + col0)       = make_float2(1.f - v00 * v00, 1.f - v01 * v01);
    *(float2*)(gd + 192 + col0) = make_float2(1.f - v10 * v10, 1.f - v11 * v11);
}

__device__ __forceinline__ void fwdL3f(const float* __restrict__ mb,
                                       const float* __restrict__ src, float* __restrict__ dxbuf,
                                       int fjq, int fcg)
{
    ull a0 = 0ull, a1 = 0ull;
    #pragma unroll 4
    for (int i = 0; i < 16; ++i) {
        const int j = 4 * i + fjq;
        const float2 m = *(const float2*)(mb + FO_M3 + j * 16 + 2 * fcg);
        const float2 hh = *(const float2*)(src + 2 * j);
        const ull mm = pk2(m.x, m.y);
        a0 = ffma2(pkdup(hh.x), mm, a0);
        a1 = ffma2(pkdup(hh.y), mm, a1);
    }
    #pragma unroll
    for (int m = 8; m <= 16; m <<= 1) {
        a0 = fadd2(a0, __shfl_xor_sync(0xffffffffu, a0, m));
        a1 = fadd2(a1, __shfl_xor_sync(0xffffffffu, a1, m));
    }
    if (fjq == 0) {
        const float2 cb = *(const float2*)(mb + FO_C3 + 2 * fcg);
        float x0l, x0h, x1l, x1h;
        upk(a0, x0l, x0h); upk(a1, x1l, x1h);
        *(float4*)(dxbuf + 4 * fcg) =
            make_float4(x0l + cb.x, x1l + cb.x, x0h + cb.y, x1h + cb.y);
    }
}

__global__ __launch_bounds__(FNT, 2)
void forward_kernel(const float* __restrict__ ts, const float* __restrict__ x0,
                    float* __restrict__ out)
{
    extern __shared__ float sm[];
    const int tid  = threadIdx.x;
    const int lane = tid & 31;
    const int wrp  = tid >> 5;
    const int fjq  = lane >> 3, fcg = lane & 7;
    const int sr   = lane >> 4, se  = lane & 15;

    float* rb = sm + FST_FLOATS + wrp * FRP;
    float* hX = rb;
    float* hY = rb + 128;

    const int grow0 = blockIdx.x * FROWS + wrp * 2;

    const float ts0 = ts[0], ts1 = ts[1], ts2 = ts[2];
    const float tst[3] = {ts0, ts1, ts2};

    float x_state = x0[(grow0 + sr) * Dd + se];
    float v_state = 0.f;
    out[(grow0 + sr) * Dd + se] = x_state;

    #pragma unroll 1
    for (int step = 0; step < 2; ++step) {
        const float tA = tst[step];
        const float hstep = tst[step + 1] - tA;
        float ksx = 0.f, ksv = 0.f, kxp = 0.f;

        #pragma unroll 1
        for (int stage = 0; stage < 4; ++stage) {
            if (stage != 2) {
                __syncthreads();
                const int tidx = step * 2 + ((stage == 0) ? 0 : ((stage == 3) ? 2 : 1));
                const float4* __restrict__ src = (const float4*)(g_F + tidx * FST_FLOATS);
                float4* dst = (float4*)sm;
                #pragma unroll 1
                for (int i = tid; i < FST_FLOATS / 4; i += FNT) dst[i] = __ldg(src + i);
                __syncthreads();
            }
            const int e = step * 4 + stage;
            float* gdbase = g_d + ((size_t)e * BATCH + grow0) * 192;

            const float coef = (stage == 0) ? 0.f : ((stage == 3) ? hstep : 0.5f * hstep);
            const float wq = (stage == 1 || stage == 2) ? 2.f : 1.f;

            hX[2 * se + sr] = x_state + coef * kxp;
            __syncwarp();
            fwd64g(sm, hX, hY, gdbase + 0,   FO_M0, FO_C0, 16, fjq, fcg);
            __syncwarp();
            fwd64g(sm, hY, hX, gdbase + 64,  FO_M1, FO_C1, 64, fjq, fcg);
            __syncwarp();
            fwd64g(sm, hX, hY, gdbase + 128, FO_M2, FO_C2, 64, fjq, fcg);
            __syncwarp();
            fwdL3f(sm, hY, hX, fjq, fcg);
            __syncwarp();

            const float dx = hX[2 * se + sr];
            float dv = dx * dx;
            #pragma unroll
            for (int m = 1; m <= 8; m <<= 1)
                dv += __shfl_xor_sync(0xffffffffu, dv, m);
            dv *= 0.5f;

            ksx += wq * dx;
            ksv += wq * dv;
            kxp = dx;
        }
        const float scl = hstep * (1.f / 6.f);
        x_state += scl * ksx;
        v_state += scl * ksv;
        out[(step + 1) * BATCH * Dd + (grow0 + sr) * Dd + se] = x_state;
    }
    if (se == 0) {
        const int base = 3 * BATCH * Dd;
        out[base + BATCH + grow0 + sr] = fabsf(v_state);
        out[base + 2 * BATCH + grow0 + sr] = 0.f;
    }
}

// ================= tangent kernel (mma.sync bf16 3-split) =================
// smem floats: [B planes 9216][Tf 2176][d 6144]
#define TS_TF 9216
#define TS_DV (TS_TF + TF_FLOATS)
#define TS_FLOATS (TS_DV + 32 * 192)
#define TS_BYTES (TS_FLOATS * 4)

__global__ __launch_bounds__(256, 2)
void tangent_kernel()
{
    extern __shared__ float sm[];
    const int tid = threadIdx.x;
    const int lane = tid & 31;
    const int wid = tid >> 5;

    const int e = blockIdx.x >> 10;
    const int rg = blockIdx.x & 1023;
    const int row0 = rg * 32;
    const int tmap[8] = {0, 1, 1, 2, 2, 3, 3, 4};
    const int tt = tmap[e];

    // copy-in
    {
        const uint4* bsrc = (const uint4*)(g_Tbf + (size_t)tt * 4 * BP_ELEMS);
        uint4* bdst = (uint4*)sm;
        #pragma unroll 1
        for (int i = tid; i < (4 * BP_ELEMS * 2) / 16; i += 256) bdst[i] = __ldg(bsrc + i);
        const uint4* fsrc = (const uint4*)(g_Tf + tt * TF_FLOATS);
        uint4* fdst = (uint4*)(sm + TS_TF);
        #pragma unroll 1
        for (int i = tid; i < TF_FLOATS / 4; i += 256) fdst[i] = __ldg(fsrc + i);
        const uint4* dsrc = (const uint4*)(g_d + ((size_t)e * BATCH + row0) * 192);
        uint4* ddst = (uint4*)(sm + TS_DV);
        #pragma unroll 1
        for (int i = tid; i < (32 * 192) / 4; i += 256) ddst[i] = __ldg(dsrc + i);
    }
    __syncthreads();

    const uint32_t smbB = smem_u32(sm);
    const float* M0f = sm + TS_TF;
    const float* M3T = sm + TS_TF + TF_M3T;

    const int g = lane >> 2;
    const int k0 = (lane & 3) * 2;
    const int lrow = lane & 15;

    #pragma unroll 1
    for (int rl = 0; rl < 4; ++rl) {
        const int r = wid * 4 + rl;
        const float* d0p = sm + TS_DV + r * 192;
        const float* d1p = d0p + 64;
        const float* d2p = d0p + 128;

        float acc1[32], acc2[32];
        #pragma unroll
        for (int i = 0; i < 32; ++i) { acc1[i] = 0.f; acc2[i] = 0.f; }

        // ---- GEMM1: U2 = (M0f .* d0) @ B1 ----
        #pragma unroll
        for (int kk = 0; kk < 4; ++kk) {
            const int K = kk * 16;
            const float2 dA = *(const float2*)(d0p + K + k0);
            const float2 dB = *(const float2*)(d0p + K + k0 + 8);
            const float2 mA = *(const float2*)(M0f + g * TF_STRIDE + K + k0);
            const float2 mB = *(const float2*)(M0f + (g + 8) * TF_STRIDE + K + k0);
            const float2 mC = *(const float2*)(M0f + g * TF_STRIDE + K + k0 + 8);
            const float2 mD = *(const float2*)(M0f + (g + 8) * TF_STRIDE + K + k0 + 8);
            uint32_t ah[4], al[4];
            ah[0] = bf2_split(mA.x * dA.x, mA.y * dA.y, al[0]);
            ah[1] = bf2_split(mB.x * dA.x, mB.y * dA.y, al[1]);
            ah[2] = bf2_split(mC.x * dB.x, mC.y * dB.y, al[2]);
            ah[3] = bf2_split(mD.x * dB.x, mD.y * dB.y, al[3]);
            const uint32_t rowaddr = smbB + (K + lrow) * (BP_STRIDE * 2);
            #pragma unroll
            for (int nt = 0; nt < 8; ++nt) {
                uint32_t bh0, bh1, bl0, bl1;
                ldmx2(rowaddr + nt * 16, bh0, bh1);
                ldmx2(rowaddr + nt * 16 + BP_ELEMS * 2, bl0, bl1);
                mma16816(acc1 + nt * 4, ah, bh0, bh1);
                mma16816(acc1 + nt * 4, al, bh0, bh1);
                mma16816(acc1 + nt * 4, ah, bl0, bl1);
            }
        }

        // ---- GEMM2: W = (M3T .* d2) @ B2 ----
        #pragma unroll
        for (int kk = 0; kk < 4; ++kk) {
            const int K = kk * 16;
            const float2 dA = *(const float2*)(d2p + K + k0);
            const float2 dB = *(const float2*)(d2p + K + k0 + 8);
            const float2 mA = *(const float2*)(M3T + g * TF_STRIDE + K + k0);
            const float2 mB = *(const float2*)(M3T + (g + 8) * TF_STRIDE + K + k0);
            const float2 mC = *(const float2*)(M3T + g * TF_STRIDE + K + k0 + 8);
            const float2 mD = *(const float2*)(M3T + (g + 8) * TF_STRIDE + K + k0 + 8);
            uint32_t ah[4], al[4];
            ah[0] = bf2_split(mA.x * dA.x, mA.y * dA.y, al[0]);
            ah[1] = bf2_split(mB.x * dA.x, mB.y * dA.y, al[1]);
            ah[2] = bf2_split(mC.x * dB.x, mC.y * dB.y, al[2]);
            ah[3] = bf2_split(mD.x * dB.x, mD.y * dB.y, al[3]);
            const uint32_t rowaddr = smbB + (K + lrow) * (BP_STRIDE * 2) + 2 * BP_ELEMS * 2;
            #pragma unroll
            for (int nt = 0; nt < 8; ++nt) {
                uint32_t bh0, bh1, bl0, bl1;
                ldmx2(rowaddr + nt * 16, bh0, bh1);
                ldmx2(rowaddr + nt * 16 + BP_ELEMS * 2, bl0, bl1);
                mma16816(acc2 + nt * 4, ah, bh0, bh1);
                mma16816(acc2 + nt * 4, al, bh0, bh1);
                mma16816(acc2 + nt * 4, ah, bl0, bl1);
            }
        }

        // ---- dl = sum U2 .* d1 .* W ----
        float dl = 0.f;
        #pragma unroll
        for (int nt = 0; nt < 8; ++nt) {
            const float2 dp = *(const float2*)(d1p + nt * 8 + k0);
            dl = fmaf(acc1[nt * 4 + 0] * dp.x, acc2[nt * 4 + 0], dl);
            dl = fmaf(acc1[nt * 4 + 1] * dp.y, acc2[nt * 4 + 1], dl);
            dl = fmaf(acc1[nt * 4 + 2] * dp.x, acc2[nt * 4 + 2], dl);
            dl = fmaf(acc1[nt * 4 + 3] * dp.y, acc2[nt * 4 + 3], dl);
        }
        #pragma unroll
        for (int m = 1; m <= 16; m <<= 1)
            dl += __shfl_xor_sync(0xffffffffu, dl, m);
        if (lane == 0)
            g_dl[e * BATCH + row0 + r] = dl;
    }
}

// ================= combine kernel =================
__global__ void combine_kernel(const float* __restrict__ ts, float* __restrict__ out)
{
    const int r = blockIdx.x * 256 + threadIdx.x;
    const float h0 = ts[1] - ts[0], h1 = ts[2] - ts[1];
    const float* dl = g_dl;
    float l = (h0 * (1.f / 6.f)) * (dl[r] + 2.f * dl[BATCH + r] + 2.f * dl[2 * BATCH + r] + dl[3 * BATCH + r])
            + (h1 * (1.f / 6.f)) * (dl[4 * BATCH + r] + 2.f * dl[5 * BATCH + r] + 2.f * dl[6 * BATCH + r] + dl[7 * BATCH + r]);
    out[3 * BATCH * Dd + r] = l;
}

extern "C" void kernel_launch(void* const* d_in, const int* in_sizes, int n_in,
                              void* d_out, int out_size) {
    const float* ts  = (const float*)d_in[0];
    const float* x0  = (const float*)d_in[1];
    const float* W0  = (const float*)d_in[2];
    const float* b0  = (const float*)d_in[3];
    const float* g0  = (const float*)d_in[4];
    const float* gb0 = (const float*)d_in[5];
    const float* hb0 = (const float*)d_in[6];
    const float* W1  = (const float*)d_in[7];
    const float* b1  = (const float*)d_in[8];
    const float* g1  = (const float*)d_in[9];
    const float* gb1 = (const float*)d_in[10];
    const float* hb1 = (const float*)d_in[11];
    const float* W2  = (const float*)d_in[12];
    const float* b2  = (const float*)d_in[13];
    const float* g2  = (const float*)d_in[14];
    const float* gb2 = (const float*)d_in[15];
    const float* hb2 = (const float*)d_in[16];
    const float* W3  = (const float*)d_in[17];
    const float* b3  = (const float*)d_in[18];
    const float* g3  = (const float*)d_in[19];
    const float* gb3 = (const float*)d_in[20];
    const float* hb3 = (const float*)d_in[21];
    float* out = (float*)d_out;

    build_kernel<<<NT, 256>>>(ts,
        W0, b0, g0, gb0, hb0,
        W1, b1, g1, gb1, hb1,
        W2, b2, g2, gb2, hb2,
        W3, b3, g3, gb3, hb3);

    cudaFuncSetAttribute(forward_kernel, cudaFuncAttributeMaxDynamicSharedMemorySize, FSMEM_BYTES);
    forward_kernel<<<BATCH / FROWS, FNT, FSMEM_BYTES>>>(ts, x0, out);

    cudaFuncSetAttribute(tangent_kernel, cudaFuncAttributeMaxDynamicSharedMemorySize, TS_BYTES);
    tangent_kernel<<<8 * 1024, 256, TS_BYTES>>>();

    combine_kernel<<<BATCH / 256, 256>>>(ts, out);
}

// round 9
// speedup vs baseline: 2.9799x; 1.2626x over previous
#include <cuda_runtime.h>
#include <cuda_bf16.h>
#include <cstdint>

#define Dd 16
#define BATCH 32768

typedef unsigned long long ull;

#define NT 5   // distinct t values

// -------- tangent-kernel constants (validated in R8) --------
#define TF_STRIDE 68
#define TF_M3T    (16 * TF_STRIDE)
#define TF_FLOATS (2 * 16 * TF_STRIDE)
#define BP_STRIDE 72
#define BP_ELEMS  (64 * BP_STRIDE)

// -------- forward-kernel bf16 weight planes (per t), element offsets --------
#define FB_W0H 0
#define FB_W0L 1152
#define FB_W1H 2304
#define FB_W1L 6912
#define FB_W2H 11520
#define FB_W2L 16128
#define FB_W3H 20736
#define FB_W3L 22272
#define FB_BF  23808
#define FB_BYTES_BF (FB_BF * 2)           // 47616
#define FB_CF  208                        // fp32 biases c0,c1,c2 (64 each) + c3 (16)
#define FWD_SMEM (FB_BYTES_BF + FB_CF * 4)

__device__ __align__(16) float g_Tf[NT * TF_FLOATS];
__device__ __align__(16) __nv_bfloat16 g_Tbf[NT * 4 * BP_ELEMS];
__device__ __align__(16) __nv_bfloat16 g_FWb[NT * FB_BF];
__device__ __align__(16) float g_FWc[NT * FB_CF];
__device__ float g_d[8ull * BATCH * 192];
__device__ float g_dl[8 * BATCH];

__device__ __forceinline__ float sigm(float x) {
    return __fdividef(1.f, 1.f + __expf(-x));
}
__device__ __forceinline__ float tanh_f(float x) {
    x = fminf(fmaxf(x, -15.f), 15.f);
    float e = __expf(-2.f * x);
    return __fdividef(1.f - e, 1.f + e);
}
__device__ __forceinline__ uint32_t smem_u32(const void* p) {
    uint32_t a;
    asm("{ .reg .u64 t; cvta.to.shared.u64 t, %1; cvt.u32.u64 %0, t; }" : "=r"(a) : "l"(p));
    return a;
}
// pack (v0 -> low half, v1 -> high half); returns hi-plane reg, lo -> residual plane
__device__ __forceinline__ uint32_t bf2_split(float v0, float v1, uint32_t& lo) {
    uint32_t h;
    asm("cvt.rn.bf16x2.f32 %0, %1, %2;" : "=r"(h) : "f"(v1), "f"(v0));
    float r0 = v0 - __uint_as_float(h << 16);
    float r1 = v1 - __uint_as_float(h & 0xFFFF0000u);
    asm("cvt.rn.bf16x2.f32 %0, %1, %2;" : "=r"(lo) : "f"(r1), "f"(r0));
    return h;
}
__device__ __forceinline__ void ldmx4(uint32_t addr, uint32_t& r0, uint32_t& r1,
                                      uint32_t& r2, uint32_t& r3) {
    asm volatile("ldmatrix.sync.aligned.m8n8.x4.trans.shared.b16 {%0,%1,%2,%3}, [%4];"
                 : "=r"(r0), "=r"(r1), "=r"(r2), "=r"(r3) : "r"(addr));
}
__device__ __forceinline__ void mma16816(float* c, const uint32_t* a, uint32_t b0, uint32_t b1) {
    asm("mma.sync.aligned.m16n8k16.row.col.f32.bf16.bf16.f32 "
        "{%0,%1,%2,%3}, {%4,%5,%6,%7}, {%8,%9}, {%0,%1,%2,%3};"
        : "+f"(c[0]), "+f"(c[1]), "+f"(c[2]), "+f"(c[3])
        : "r"(a[0]), "r"(a[1]), "r"(a[2]), "r"(a[3]), "r"(b0), "r"(b1));
}
__device__ __forceinline__ void mma3(float* c, const uint32_t* ah, const uint32_t* al,
                                     uint32_t bh0, uint32_t bh1, uint32_t bl0, uint32_t bl1) {
    mma16816(c, ah, bh0, bh1);
    mma16816(c, al, bh0, bh1);
    mma16816(c, ah, bl0, bl1);
}

// ---------------- build kernel: one block per distinct t ----------------
__global__ void build_kernel(const float* __restrict__ ts,
    const float* __restrict__ W0, const float* __restrict__ b0, const float* __restrict__ g0, const float* __restrict__ gb0, const float* __restrict__ hb0,
    const float* __restrict__ W1, const float* __restrict__ b1, const float* __restrict__ g1, const float* __restrict__ gb1, const float* __restrict__ hb1,
    const float* __restrict__ W2, const float* __restrict__ b2, const float* __restrict__ g2, const float* __restrict__ gb2, const float* __restrict__ hb2,
    const float* __restrict__ W3, const float* __restrict__ b3, const float* __restrict__ g3, const float* __restrict__ gb3, const float* __restrict__ hb3)
{
    const int tt = blockIdx.x;
    const float ts0 = ts[0], ts1 = ts[1], ts2 = ts[2];
    float t;
    if (tt == 0) t = ts0;
    else if (tt == 1) t = ts0 + 0.5f * (ts1 - ts0);
    else if (tt == 2) t = ts1;
    else if (tt == 3) t = ts1 + 0.5f * (ts2 - ts1);
    else t = ts2;

    float* tf = g_Tf + tt * TF_FLOATS;
    __nv_bfloat16* bp = g_Tbf + (size_t)tt * 4 * BP_ELEMS;
    __nv_bfloat16* fw = g_FWb + (size_t)tt * FB_BF;
    float* fc = g_FWc + tt * FB_CF;
    const int tid = threadIdx.x;

    for (int i = tid; i < 1024; i += blockDim.x) {
        int j = i >> 6, c = i & 63;
        float v = W0[i] * sigm(t * g0[c] + gb0[c]);
        tf[j * TF_STRIDE + c] = v;                  // M0f[tx=j][a=c]
        __nv_bfloat16 h = __float2bfloat16_rn(v);
        __nv_bfloat16 l = __float2bfloat16_rn(v - __bfloat162float(h));
        fw[FB_W0H + j * 72 + c] = h;
        fw[FB_W0L + j * 72 + c] = l;
    }
    for (int i = tid; i < 4096; i += blockDim.x) {
        int a = i >> 6, b = i & 63;
        float v = W1[i] * sigm(t * g1[b] + gb1[b]);
        __nv_bfloat16 h = __float2bfloat16_rn(v);
        __nv_bfloat16 l = __float2bfloat16_rn(v - __bfloat162float(h));
        bp[0 * BP_ELEMS + a * BP_STRIDE + b] = h;   // tangent B1[k=a][n=b]
        bp[1 * BP_ELEMS + a * BP_STRIDE + b] = l;
        fw[FB_W1H + a * 72 + b] = h;                // forward B [k=a][n=b]
        fw[FB_W1L + a * 72 + b] = l;
    }
    for (int i = tid; i < 4096; i += blockDim.x) {
        int b = i >> 6, c = i & 63;
        float v = W2[i] * sigm(t * g2[c] + gb2[c]);
        __nv_bfloat16 h = __float2bfloat16_rn(v);
        __nv_bfloat16 l = __float2bfloat16_rn(v - __bfloat162float(h));
        bp[2 * BP_ELEMS + c * BP_STRIDE + b] = h;   // tangent B2[k=c][n=b]
        bp[3 * BP_ELEMS + c * BP_STRIDE + b] = l;
        fw[FB_W2H + b * 72 + c] = h;                // forward B [k=b][n=c]
        fw[FB_W2L + b * 72 + c] = l;
    }
    for (int i = tid; i < 1024; i += blockDim.x) {
        int j = i >> 4, e = i & 15;
        float v = W3[i] * sigm(t * g3[e] + gb3[e]);
        tf[TF_M3T + e * TF_STRIDE + j] = v;         // M3T[tx=e][c=j]
        __nv_bfloat16 h = __float2bfloat16_rn(v);
        __nv_bfloat16 l = __float2bfloat16_rn(v - __bfloat162float(h));
        fw[FB_W3H + j * 24 + e] = h;
        fw[FB_W3L + j * 24 + e] = l;
    }
    if (tid < 64) {
        float s0 = sigm(t * g0[tid] + gb0[tid]);
        float s1 = sigm(t * g1[tid] + gb1[tid]);
        float s2 = sigm(t * g2[tid] + gb2[tid]);
        fc[0 + tid]   = b0[tid] * s0 + t * hb0[tid];
        fc[64 + tid]  = b1[tid] * s1 + t * hb1[tid];
        fc[128 + tid] = b2[tid] * s2 + t * hb2[tid];
        if (tid < 16) {
            float s3 = sigm(t * g3[tid] + gb3[tid]);
            fc[192 + tid] = b3[tid] * s3 + t * hb3[tid];
        }
    }
}

// ================= forward kernel (mma.sync, registers-only state) =================
// epilogue: bias+tanh, write d's, repack next-layer A fragments
__device__ __forceinline__ void fwd_epi(const float* acc, const float* Cv,
                                        float* gdA, float* gdB, int tig,
                                        uint32_t* fh, uint32_t* fl)
{
    #pragma unroll
    for (int nt = 0; nt < 8; ++nt) {
        const int col = nt * 8 + 2 * tig;
        const float b0 = Cv[col], b1 = Cv[col + 1];
        const float h0 = tanh_f(acc[nt * 4 + 0] + b0);
        const float h1 = tanh_f(acc[nt * 4 + 1] + b1);
        const float h2 = tanh_f(acc[nt * 4 + 2] + b0);
        const float h3 = tanh_f(acc[nt * 4 + 3] + b1);
        *(float2*)(gdA + col) = make_float2(1.f - h0 * h0, 1.f - h1 * h1);
        *(float2*)(gdB + col) = make_float2(1.f - h2 * h2, 1.f - h3 * h3);
        const int kk = nt >> 1, hf = nt & 1;
        fh[kk * 4 + hf * 2 + 0] = bf2_split(h0, h1, fl[kk * 4 + hf * 2 + 0]);
        fh[kk * 4 + hf * 2 + 1] = bf2_split(h2, h3, fl[kk * 4 + hf * 2 + 1]);
    }
}

__global__ __launch_bounds__(128, 2)
void forward_kernel(const float* __restrict__ ts, const float* __restrict__ x0,
                    float* __restrict__ out)
{
    extern __shared__ char smc[];
    float* C = (float*)(smc + FB_BYTES_BF);

    const int tid  = threadIdx.x;
    const int lane = tid & 31;
    const int wid  = tid >> 5;
    const int g = lane >> 2, tig = lane & 3;
    const int d0c = 2 * tig, d1c = 8 + 2 * tig;

    const int rowA = blockIdx.x * 64 + wid * 16 + g;
    const int rowB = rowA + 8;

    const uint32_t smb = smem_u32(smc);
    const uint32_t lrow = lane & 15, lcol = (lane >> 4) * 16;

    const float ts0 = ts[0], ts1 = ts[1], ts2 = ts[2];
    const float tst[3] = {ts0, ts1, ts2};

    // state in frag layout: slots {0,1}=(rowA,d0..), {2,3}=(rowB,d0..), {4,5}=(rowA,d1..), {6,7}=(rowB,d1..)
    float xs[8];
    {
        float2 p0 = *(const float2*)(x0 + rowA * 16 + d0c);
        float2 p1 = *(const float2*)(x0 + rowB * 16 + d0c);
        float2 p2 = *(const float2*)(x0 + rowA * 16 + d1c);
        float2 p3 = *(const float2*)(x0 + rowB * 16 + d1c);
        xs[0] = p0.x; xs[1] = p0.y; xs[2] = p1.x; xs[3] = p1.y;
        xs[4] = p2.x; xs[5] = p2.y; xs[6] = p3.x; xs[7] = p3.y;
        *(float2*)(out + rowA * 16 + d0c) = p0;
        *(float2*)(out + rowB * 16 + d0c) = p1;
        *(float2*)(out + rowA * 16 + d1c) = p2;
        *(float2*)(out + rowB * 16 + d1c) = p3;
    }
    float vA = 0.f, vB = 0.f;
    int ptt = -1;

    #pragma unroll 1
    for (int step = 0; step < 2; ++step) {
        const float tA = tst[step];
        const float hstep = tst[step + 1] - tA;
        float ksx[8], kxp[8];
        #pragma unroll
        for (int i = 0; i < 8; ++i) { ksx[i] = 0.f; kxp[i] = 0.f; }
        float ksvA = 0.f, ksvB = 0.f;

        #pragma unroll 1
        for (int stage = 0; stage < 4; ++stage) {
            const int tt = step * 2 + ((stage == 0) ? 0 : ((stage == 3) ? 2 : 1));
            if (tt != ptt) {
                __syncthreads();
                const uint4* src = (const uint4*)(g_FWb + (size_t)tt * FB_BF);
                uint4* dst = (uint4*)smc;
                #pragma unroll 1
                for (int i = tid; i < FB_BYTES_BF / 16; i += 128) dst[i] = __ldg(src + i);
                const uint4* cs = (const uint4*)(g_FWc + tt * FB_CF);
                uint4* cd = (uint4*)(smc + FB_BYTES_BF);
                if (tid < FB_CF / 4) cd[tid] = __ldg(cs + tid);
                __syncthreads();
                ptt = tt;
            }
            const int e = step * 4 + stage;
            const float coef = (stage == 0) ? 0.f : ((stage == 3) ? hstep : 0.5f * hstep);
            const float wq = (stage == 1 || stage == 2) ? 2.f : 1.f;

            float* gdA = g_d + ((size_t)e * BATCH + rowA) * 192;
            float* gdB = g_d + ((size_t)e * BATCH + rowB) * 192;

            // ---- L0 A-frags from state regs ----
            uint32_t fh[16], fl[16];
            {
                float xe[8];
                #pragma unroll
                for (int i = 0; i < 8; ++i) xe[i] = xs[i] + coef * kxp[i];
                fh[0] = bf2_split(xe[0], xe[1], fl[0]);
                fh[1] = bf2_split(xe[2], xe[3], fl[1]);
                fh[2] = bf2_split(xe[4], xe[5], fl[2]);
                fh[3] = bf2_split(xe[6], xe[7], fl[3]);
            }
            float acc[32];

            // ---- L0: k=16 ----
            #pragma unroll
            for (int i = 0; i < 32; ++i) acc[i] = 0.f;
            {
                const uint32_t rb_ = smb + FB_W0H * 2 + lrow * 144 + lcol;
                #pragma unroll
                for (int p = 0; p < 4; ++p) {
                    uint32_t h0, h1, h2, h3, l0, l1, l2, l3;
                    ldmx4(rb_ + p * 32, h0, h1, h2, h3);
                    ldmx4(rb_ + p * 32 + 2304, l0, l1, l2, l3);
                    mma3(acc + (2 * p) * 4, fh, fl, h0, h1, l0, l1);
                    mma3(acc + (2 * p + 1) * 4, fh, fl, h2, h3, l2, l3);
                }
            }
            fwd_epi(acc, C + 0, gdA + 0, gdB + 0, tig, fh, fl);

            // ---- L1: k=64 ----
            #pragma unroll
            for (int i = 0; i < 32; ++i) acc[i] = 0.f;
            {
                const uint32_t rb_ = smb + FB_W1H * 2 + lrow * 144 + lcol;
                #pragma unroll
                for (int kk = 0; kk < 4; ++kk) {
                    const uint32_t rk = rb_ + kk * 16 * 144;
                    #pragma unroll
                    for (int p = 0; p < 4; ++p) {
                        uint32_t h0, h1, h2, h3, l0, l1, l2, l3;
                        ldmx4(rk + p * 32, h0, h1, h2, h3);
                        ldmx4(rk + p * 32 + 9216, l0, l1, l2, l3);
                        mma3(acc + (2 * p) * 4, fh + kk * 4, fl + kk * 4, h0, h1, l0, l1);
                        mma3(acc + (2 * p + 1) * 4, fh + kk * 4, fl + kk * 4, h2, h3, l2, l3);
                    }
                }
            }
            fwd_epi(acc, C + 64, gdA + 64, gdB + 64, tig, fh, fl);

            // ---- L2: k=64 ----
            #pragma unroll
            for (int i = 0; i < 32; ++i) acc[i] = 0.f;
            {
                const uint32_t rb_ = smb + FB_W2H * 2 + lrow * 144 + lcol;
                #pragma unroll
                for (int kk = 0; kk < 4; ++kk) {
                    const uint32_t rk = rb_ + kk * 16 * 144;
                    #pragma unroll
                    for (int p = 0; p < 4; ++p) {
                        uint32_t h0, h1, h2, h3, l0, l1, l2, l3;
                        ldmx4(rk + p * 32, h0, h1, h2, h3);
                        ldmx4(rk + p * 32 + 9216, l0, l1, l2, l3);
                        mma3(acc + (2 * p) * 4, fh + kk * 4, fl + kk * 4, h0, h1, l0, l1);
                        mma3(acc + (2 * p + 1) * 4, fh + kk * 4, fl + kk * 4, h2, h3, l2, l3);
                    }
                }
            }
            fwd_epi(acc, C + 128, gdA + 128, gdB + 128, tig, fh, fl);

            // ---- L3: k=64, n=16, no tanh ----
            float a3[8];
            #pragma unroll
            for (int i = 0; i < 8; ++i) a3[i] = 0.f;
            {
                const uint32_t rb_ = smb + FB_W3H * 2 + lrow * 48 + lcol;
                #pragma unroll
                for (int kk = 0; kk < 4; ++kk) {
                    uint32_t h0, h1, h2, h3, l0, l1, l2, l3;
                    ldmx4(rb_ + kk * 16 * 48, h0, h1, h2, h3);
                    ldmx4(rb_ + kk * 16 * 48 + 3072, l0, l1, l2, l3);
                    mma3(a3 + 0, fh + kk * 4, fl + kk * 4, h0, h1, l0, l1);
                    mma3(a3 + 4, fh + kk * 4, fl + kk * 4, h2, h3, l2, l3);
                }
            }
            float dxv[8];
            dxv[0] = a3[0] + C[192 + d0c];  dxv[1] = a3[1] + C[192 + d0c + 1];
            dxv[2] = a3[2] + C[192 + d0c];  dxv[3] = a3[3] + C[192 + d0c + 1];
            dxv[4] = a3[4] + C[192 + d1c];  dxv[5] = a3[5] + C[192 + d1c + 1];
            dxv[6] = a3[6] + C[192 + d1c];  dxv[7] = a3[7] + C[192 + d1c + 1];

            float dvA = dxv[0] * dxv[0] + dxv[1] * dxv[1] + dxv[4] * dxv[4] + dxv[5] * dxv[5];
            float dvB = dxv[2] * dxv[2] + dxv[3] * dxv[3] + dxv[6] * dxv[6] + dxv[7] * dxv[7];
            dvA += __shfl_xor_sync(0xffffffffu, dvA, 1);
            dvA += __shfl_xor_sync(0xffffffffu, dvA, 2);
            dvB += __shfl_xor_sync(0xffffffffu, dvB, 1);
            dvB += __shfl_xor_sync(0xffffffffu, dvB, 2);

            #pragma unroll
            for (int i = 0; i < 8; ++i) { ksx[i] += wq * dxv[i]; kxp[i] = dxv[i]; }
            ksvA += wq * dvA;
            ksvB += wq * dvB;
        }

        const float scl = hstep * (1.f / 6.f);
        #pragma unroll
        for (int i = 0; i < 8; ++i) xs[i] += scl * ksx[i];
        vA += scl * 0.5f * ksvA;
        vB += scl * 0.5f * ksvB;

        float* os = out + (step + 1) * BATCH * Dd;
        *(float2*)(os + rowA * 16 + d0c) = make_float2(xs[0], xs[1]);
        *(float2*)(os + rowB * 16 + d0c) = make_float2(xs[2], xs[3]);
        *(float2*)(os + rowA * 16 + d1c) = make_float2(xs[4], xs[5]);
        *(float2*)(os + rowB * 16 + d1c) = make_float2(xs[6], xs[7]);
    }

    if (tig == 0) {
        const int base = 3 * BATCH * Dd;
        out[base + BATCH + rowA] = fabsf(vA);
        out[base + BATCH + rowB] = fabsf(vB);
        out[base + 2 * BATCH + rowA] = 0.f;
        out[base + 2 * BATCH + rowB] = 0.f;
    }
}

// ================= tangent kernel (mma.sync bf16 3-split; x4 B-loads) =================
#define TS_TF 9216
#define TS_DV (TS_TF + TF_FLOATS)
#define TS_FLOATS (TS_DV + 32 * 192)
#define TS_BYTES (TS_FLOATS * 4)

__global__ __launch_bounds__(256, 2)
void tangent_kernel()
{
    extern __shared__ float sm[];
    const int tid = threadIdx.x;
    const int lane = tid & 31;
    const int wid = tid >> 5;

    const int e = blockIdx.x >> 10;
    const int rg = blockIdx.x & 1023;
    const int row0 = rg * 32;
    const int tmap[8] = {0, 1, 1, 2, 2, 3, 3, 4};
    const int tt = tmap[e];

    {
        const uint4* bsrc = (const uint4*)(g_Tbf + (size_t)tt * 4 * BP_ELEMS);
        uint4* bdst = (uint4*)sm;
        #pragma unroll 1
        for (int i = tid; i < (4 * BP_ELEMS * 2) / 16; i += 256) bdst[i] = __ldg(bsrc + i);
        const uint4* fsrc = (const uint4*)(g_Tf + tt * TF_FLOATS);
        uint4* fdst = (uint4*)(sm + TS_TF);
        #pragma unroll 1
        for (int i = tid; i < TF_FLOATS / 4; i += 256) fdst[i] = __ldg(fsrc + i);
        const uint4* dsrc = (const uint4*)(g_d + ((size_t)e * BATCH + row0) * 192);
        uint4* ddst = (uint4*)(sm + TS_DV);
        #pragma unroll 1
        for (int i = tid; i < (32 * 192) / 4; i += 256) ddst[i] = __ldg(dsrc + i);
    }
    __syncthreads();

    const uint32_t smbB = smem_u32(sm);
    const float* M0f = sm + TS_TF;
    const float* M3T = sm + TS_TF + TF_M3T;

    const int g = lane >> 2;
    const int k0 = (lane & 3) * 2;
    const uint32_t lrow = lane & 15, lcol = (lane >> 4) * 16;

    #pragma unroll 1
    for (int rl = 0; rl < 4; ++rl) {
        const int r = wid * 4 + rl;
        const float* d0p = sm + TS_DV + r * 192;
        const float* d1p = d0p + 64;
        const float* d2p = d0p + 128;

        float acc1[32], acc2[32];
        #pragma unroll
        for (int i = 0; i < 32; ++i) { acc1[i] = 0.f; acc2[i] = 0.f; }

        // ---- GEMM1: U2 = (M0f .* d0) @ B1 ----
        #pragma unroll
        for (int kk = 0; kk < 4; ++kk) {
            const int K = kk * 16;
            const float2 dA = *(const float2*)(d0p + K + k0);
            const float2 dB = *(const float2*)(d0p + K + k0 + 8);
            const float2 mA = *(const float2*)(M0f + g * TF_STRIDE + K + k0);
            const float2 mB = *(const float2*)(M0f + (g + 8) * TF_STRIDE + K + k0);
            const float2 mC = *(const float2*)(M0f + g * TF_STRIDE + K + k0 + 8);
            const float2 mD = *(const float2*)(M0f + (g + 8) * TF_STRIDE + K + k0 + 8);
            uint32_t ah[4], al[4];
            ah[0] = bf2_split(mA.x * dA.x, mA.y * dA.y, al[0]);
            ah[1] = bf2_split(mB.x * dA.x, mB.y * dA.y, al[1]);
            ah[2] = bf2_split(mC.x * dB.x, mC.y * dB.y, al[2]);
            ah[3] = bf2_split(mD.x * dB.x, mD.y * dB.y, al[3]);
            const uint32_t rowaddr = smbB + (K + lrow) * (BP_STRIDE * 2) + lcol;
            #pragma unroll
            for (int p = 0; p < 4; ++p) {
                uint32_t h0, h1, h2, h3, l0, l1, l2, l3;
                ldmx4(rowaddr + p * 32, h0, h1, h2, h3);
                ldmx4(rowaddr + p * 32 + BP_ELEMS * 2, l0, l1, l2, l3);
                mma3(acc1 + (2 * p) * 4, ah, al, h0, h1, l0, l1);
                mma3(acc1 + (2 * p + 1) * 4, ah, al, h2, h3, l2, l3);
            }
        }

        // ---- GEMM2: W = (M3T .* d2) @ B2 ----
        #pragma unroll
        for (int kk = 0; kk < 4; ++kk) {
            const int K = kk * 16;
            const float2 dA = *(const float2*)(d2p + K + k0);
            const float2 dB = *(const float2*)(d2p + K + k0 + 8);
            const float2 mA = *(const float2*)(M3T + g * TF_STRIDE + K + k0);
            const float2 mB = *(const float2*)(M3T + (g + 8) * TF_STRIDE + K + k0);
            const float2 mC = *(const float2*)(M3T + g * TF_STRIDE + K + k0 + 8);
            const float2 mD = *(const float2*)(M3T + (g + 8) * TF_STRIDE + K + k0 + 8);
            uint32_t ah[4], al[4];
            ah[0] = bf2_split(mA.x * dA.x, mA.y * dA.y, al[0]);
            ah[1] = bf2_split(mB.x * dA.x, mB.y * dA.y, al[1]);
            ah[2] = bf2_split(mC.x * dB.x, mC.y * dB.y, al[2]);
            ah[3] = bf2_split(mD.x * dB.x, mD.y * dB.y, al[3]);
            const uint32_t rowaddr = smbB + (K + lrow) * (BP_STRIDE * 2) + lcol + 2 * BP_ELEMS * 2;
            #pragma unroll
            for (int p = 0; p < 4; ++p) {
                uint32_t h0, h1, h2, h3, l0, l1, l2, l3;
                ldmx4(rowaddr + p * 32, h0, h1, h2, h3);
                ldmx4(rowaddr + p * 32 + BP_ELEMS * 2, l0, l1, l2, l3);
                mma3(acc2 + (2 * p) * 4, ah, al, h0, h1, l0, l1);
                mma3(acc2 + (2 * p + 1) * 4, ah, al, h2, h3, l2, l3);
            }
        }

        // ---- dl = sum U2 .* d1 .* W ----
        float dl = 0.f;
        #pragma unroll
        for (int nt = 0; nt < 8; ++nt) {
            const float2 dp = *(const float2*)(d1p + nt * 8 + k0);
            dl = fmaf(acc1[nt * 4 + 0] * dp.x, acc2[nt * 4 + 0], dl);
            dl = fmaf(acc1[nt * 4 + 1] * dp.y, acc2[nt * 4 + 1], dl);
            dl = fmaf(acc1[nt * 4 + 2] * dp.x, acc2[nt * 4 + 2], dl);
            dl = fmaf(acc1[nt * 4 + 3] * dp.y, acc2[nt * 4 + 3], dl);
        }
        #pragma unroll
        for (int m = 1; m <= 16; m <<= 1)
            dl += __shfl_xor_sync(0xffffffffu, dl, m);
        if (lane == 0)
            g_dl[e * BATCH + row0 + r] = dl;
    }
}

// ================= combine kernel =================
__global__ void combine_kernel(const float* __restrict__ ts, float* __restrict__ out)
{
    const int r = blockIdx.x * 256 + threadIdx.x;
    const float h0 = ts[1] - ts[0], h1 = ts[2] - ts[1];
    const float* dl = g_dl;
    float l = (h0 * (1.f / 6.f)) * (dl[r] + 2.f * dl[BATCH + r] + 2.f * dl[2 * BATCH + r] + dl[3 * BATCH + r])
            + (h1 * (1.f / 6.f)) * (dl[4 * BATCH + r] + 2.f * dl[5 * BATCH + r] + 2.f * dl[6 * BATCH + r] + dl[7 * BATCH + r]);
    out[3 * BATCH * Dd + r] = l;
}

extern "C" void kernel_launch(void* const* d_in, const int* in_sizes, int n_in,
                              void* d_out, int out_size) {
    const float* ts  = (const float*)d_in[0];
    const float* x0  = (const float*)d_in[1];
    const float* W0  = (const float*)d_in[2];
    const float* b0  = (const float*)d_in[3];
    const float* g0  = (const float*)d_in[4];
    const float* gb0 = (const float*)d_in[5];
    const float* hb0 = (const float*)d_in[6];
    const float* W1  = (const float*)d_in[7];
    const float* b1  = (const float*)d_in[8];
    const float* g1  = (const float*)d_in[9];
    const float* gb1 = (const float*)d_in[10];
    const float* hb1 = (const float*)d_in[11];
    const float* W2  = (const float*)d_in[12];
    const float* b2  = (const float*)d_in[13];
    const float* g2  = (const float*)d_in[14];
    const float* gb2 = (const float*)d_in[15];
    const float* hb2 = (const float*)d_in[16];
    const float* W3  = (const float*)d_in[17];
    const float* b3  = (const float*)d_in[18];
    const float* g3  = (const float*)d_in[19];
    const float* gb3 = (const float*)d_in[20];
    const float* hb3 = (const float*)d_in[21];
    float* out = (float*)d_out;

    build_kernel<<<NT, 256>>>(ts,
        W0, b0, g0, gb0, hb0,
        W1, b1, g1, gb1, hb1,
        W2, b2, g2, gb2, hb2,
        W3, b3, g3, gb3, hb3);

    cudaFuncSetAttribute(forward_kernel, cudaFuncAttributeMaxDynamicSharedMemorySize, FWD_SMEM);
    forward_kernel<<<BATCH / 64, 128, FWD_SMEM>>>(ts, x0, out);

    cudaFuncSetAttribute(tangent_kernel, cudaFuncAttributeMaxDynamicSharedMemorySize, TS_BYTES);
    tangent_kernel<<<8 * 1024, 256, TS_BYTES>>>();

    combine_kernel<<<BATCH / 256, 256>>>(ts, out);
}